// round 1
// baseline (speedup 1.0000x reference)
#include <cuda_runtime.h>
#include <cuda_bf16.h>
#include <math.h>
#include <float.h>

// Problem constants
#define BATCH 4
#define SEQ   512
#define CDIM  768
#define NHEAD 12
#define HS    64
#define BH    (BATCH*NHEAD)      // 48
#define TOPM  16
#define MAXSZ 8

// Scratch (device globals; allocation is forbidden)
__device__ float g_q[BH*SEQ*HS];     // [b,h,t,d]
__device__ float g_k[BH*SEQ*HS];
__device__ float g_v[BH*SEQ*HS];
__device__ float g_y[BATCH*SEQ*CDIM]; // [b,t,c]

// ---------------------------------------------------------------------------
// Tiled SGEMM: C[M,N] = A[M,K] @ W[K,N] + bias[N]
// mode 0: scatter into g_q/g_k/g_v   ([B,T,3C] -> [B,H,T,64] x3)
// mode 1: plain store to Cout
// Requires M%64==0, N%64==0, K%16==0 (true for both calls).
// ---------------------------------------------------------------------------
__global__ __launch_bounds__(256)
void sgemm_kernel(const float* __restrict__ A, const float* __restrict__ W,
                  const float* __restrict__ bias, float* __restrict__ Cout,
                  int M, int N, int K, int mode)
{
    __shared__ float As[16][68];   // padded to avoid bank conflicts on transpose store
    __shared__ float Bs[16][64];

    const float* Ain = A ? A : g_y;

    int tid = threadIdx.x;
    int bm = blockIdx.y, bn = blockIdx.x;
    int ty = tid >> 4, tx = tid & 15;

    float acc[4][4];
#pragma unroll
    for (int i = 0; i < 4; i++)
#pragma unroll
        for (int j = 0; j < 4; j++) acc[i][j] = 0.f;

    for (int k0 = 0; k0 < K; k0 += 16) {
#pragma unroll
        for (int r = 0; r < 4; r++) {
            int idx = tid + 256*r;
            int row = idx >> 4, col = idx & 15;
            As[col][row] = Ain[(size_t)(bm*64 + row)*K + k0 + col];
        }
#pragma unroll
        for (int r = 0; r < 4; r++) {
            int idx = tid + 256*r;
            int row = idx >> 6, col = idx & 63;
            Bs[row][col] = W[(size_t)(k0 + row)*N + bn*64 + col];
        }
        __syncthreads();
#pragma unroll
        for (int kk = 0; kk < 16; kk++) {
            float a[4], b[4];
#pragma unroll
            for (int i = 0; i < 4; i++) a[i] = As[kk][ty*4 + i];
#pragma unroll
            for (int j = 0; j < 4; j++) b[j] = Bs[kk][tx*4 + j];
#pragma unroll
            for (int i = 0; i < 4; i++)
#pragma unroll
                for (int j = 0; j < 4; j++) acc[i][j] = fmaf(a[i], b[j], acc[i][j]);
        }
        __syncthreads();
    }

#pragma unroll
    for (int i = 0; i < 4; i++) {
        int row = bm*64 + ty*4 + i;
#pragma unroll
        for (int j = 0; j < 4; j++) {
            int col = bn*64 + tx*4 + j;
            float v = acc[i][j] + bias[col];
            if (mode == 1) {
                Cout[(size_t)row*N + col] = v;
            } else {
                int sect = col / CDIM;          // 0=q 1=k 2=v
                int c = col - sect*CDIM;
                int h = c >> 6;
                int dd = c & 63;
                int bb = row >> 9;              // row = b*512 + t
                int t  = row & 511;
                float* dst = (sect == 0) ? g_q : (sect == 1 ? g_k : g_v);
                dst[(((size_t)(bb*NHEAD + h))*SEQ + t)*HS + dd] = v;
            }
        }
    }
}

// ---------------------------------------------------------------------------
// DPP greedy selection attention. One block per (b,h,token). 256 threads.
// ---------------------------------------------------------------------------
__global__ __launch_bounds__(256)
void dpp_kernel()
{
    const int i  = blockIdx.x;   // token
    const int bh = blockIdx.y;   // b*12 + h
    const int tid = threadIdx.x;

    const float* __restrict__ kb = g_k + (size_t)bh*SEQ*HS;
    const float* __restrict__ vb = g_v + (size_t)bh*SEQ*HS;
    const float* __restrict__ qi = g_q + ((size_t)bh*SEQ + i)*HS;

    __shared__ float sq[64];
    __shared__ float ssim[SEQ];
    __shared__ float G[17][17];
    __shared__ int   topIdx[16];
    __shared__ float redV[8];
    __shared__ int   redI[8];
    __shared__ float sS[16];
    __shared__ int   sel[8];
    __shared__ int   s_count;
    __shared__ float s_curS;
    __shared__ int   s_stop;
    __shared__ unsigned s_avail;

    if (tid < 64) sq[tid] = qi[tid];
    __syncthreads();

    // sim[j] = k[j] . q_i for j <= i
    const int nvalid = i + 1;
    for (int j = tid; j < nvalid; j += 256) {
        const float4* kr = (const float4*)(kb + (size_t)j*HS);
        float a = 0.f;
#pragma unroll
        for (int c = 0; c < 16; c++) {
            float4 kv = kr[c];
            a = fmaf(kv.x, sq[4*c+0], a);
            a = fmaf(kv.y, sq[4*c+1], a);
            a = fmaf(kv.z, sq[4*c+2], a);
            a = fmaf(kv.w, sq[4*c+3], a);
        }
        ssim[j] = a;
    }
    __syncthreads();

    // top-16, ties -> lower index first (jax.lax.top_k semantics)
    for (int t = 0; t < 16; t++) {
        float bv = -INFINITY; int bi = 0x7fffffff;
        for (int j = tid; j < nvalid; j += 256) {
            float v = ssim[j];
            if (v > bv) { bv = v; bi = j; }   // ascending j -> lowest index kept on tie
        }
#pragma unroll
        for (int off = 16; off; off >>= 1) {
            float ov = __shfl_down_sync(0xffffffffu, bv, off);
            int   oi = __shfl_down_sync(0xffffffffu, bi, off);
            if (ov > bv || (ov == bv && oi < bi)) { bv = ov; bi = oi; }
        }
        int lane = tid & 31, w = tid >> 5;
        if (lane == 0) { redV[w] = bv; redI[w] = bi; }
        __syncthreads();
        if (tid == 0) {
            bv = redV[0]; bi = redI[0];
#pragma unroll
            for (int w2 = 1; w2 < 8; w2++)
                if (redV[w2] > bv || (redV[w2] == bv && redI[w2] < bi)) { bv = redV[w2]; bi = redI[w2]; }
            if (t < nvalid) { topIdx[t] = bi; ssim[bi] = -INFINITY; }
            else            { topIdx[t] = -1; }
        }
        __syncthreads();
    }

    // availability mask (finite value slot && candidate != i)
    if (tid < 32) {
        bool a = (tid < 16) && (topIdx[tid] >= 0) && (topIdx[tid] != i);
        unsigned m = __ballot_sync(0xffffffffu, a);
        if (tid == 0) s_avail = m & 0xffffu;
    }

    // 17x17 gram of {cand 0..15, i}; invalid cand slots mapped to i (never used)
    for (int p = tid; p < 289; p += 256) {
        int a = p / 17, b = p % 17;
        int ta = (a == 16) ? i : (topIdx[a] >= 0 ? topIdx[a] : i);
        int tb = (b == 16) ? i : (topIdx[b] >= 0 ? topIdx[b] : i);
        const float4* ra = (const float4*)(kb + (size_t)ta*HS);
        const float4* rb = (const float4*)(kb + (size_t)tb*HS);
        float acc = 0.f;
#pragma unroll
        for (int c = 0; c < 16; c++) {
            float4 x = ra[c], y = rb[c];
            acc = fmaf(x.x, y.x, acc);
            acc = fmaf(x.y, y.y, acc);
            acc = fmaf(x.z, y.z, acc);
            acc = fmaf(x.w, y.w, acc);
        }
        G[a][b] = acc;
    }

    if (tid == 0) {
        sel[0] = 16;            // local id of token i
        s_count = 1;
        s_stop = 0;
    }
    __syncthreads();
    if (tid == 0) s_curS = -logf(G[16][16] + 1e-6f);
    __syncthreads();

    // greedy loop (up to 7 additions)
    for (int step = 0; step < MAXSZ - 1; step++) {
        int count = s_count;
        unsigned avail = s_avail;
        float sv = -INFINITY;
        if (tid < 16 && ((avail >> tid) & 1u)) {
            int n = count + 1;
            int vidx[8];
            for (int r = 0; r < count; r++) vidx[r] = sel[r];
            vidx[count] = tid;
            float A[8][8];
            for (int r = 0; r < n; r++)
                for (int c = 0; c < n; c++)
                    A[r][c] = G[vidx[r]][vidx[c]];
            // LU with partial pivoting -> det
            float det = 1.f;
            for (int kk = 0; kk < n; kk++) {
                int p = kk; float mx = fabsf(A[kk][kk]);
                for (int r = kk + 1; r < n; r++) {
                    float av = fabsf(A[r][kk]);
                    if (av > mx) { mx = av; p = r; }
                }
                if (p != kk) {
                    for (int c = 0; c < n; c++) { float tmp = A[kk][c]; A[kk][c] = A[p][c]; A[p][c] = tmp; }
                    det = -det;
                }
                float piv = A[kk][kk];
                det *= piv;
                if (piv != 0.f) {
                    for (int r = kk + 1; r < n; r++) {
                        float f = A[r][kk] / piv;
                        for (int c = kk + 1; c < n; c++) A[r][c] = fmaf(-f, A[kk][c], A[r][c]);
                    }
                }
            }
            sv = -logf(det + 1e-6f) / (float)n;   // may be NaN if det+eps <= 0, like the ref
        }
        if (tid < 16) sS[tid] = sv;
        __syncthreads();
        if (tid == 0) {
            // argmax: NaN treated as max, first index wins ties (numpy/jax argmax)
            int bestm = 0; float bs = sS[0];
            for (int m = 1; m < 16; m++) {
                float v = sS[m];
                bool better;
                if (isnan(bs)) better = false;
                else if (isnan(v)) better = true;
                else better = (v > bs);
                if (better) { bs = v; bestm = m; }
            }
            bool anyAvail = (s_avail != 0u);
            bool accept = anyAvail && ((bs > s_curS) || (s_count < 2));
            if (accept) {
                sel[s_count] = bestm;
                s_count = s_count + 1;
                s_curS = bs;
                s_avail &= ~(1u << bestm);
            } else {
                s_stop = 1;
            }
        }
        __syncthreads();
        if (s_stop) break;
    }

    // y_i = mean of selected v rows
    if (tid < 64) {
        int count = s_count;
        float acc = 0.f;
        for (int r = 0; r < count; r++) {
            int lv = sel[r];
            int gj = (lv == 16) ? i : topIdx[lv];
            acc += vb[(size_t)gj*HS + tid];
        }
        int bb = bh / NHEAD, h = bh % NHEAD;
        g_y[((size_t)(bb*SEQ + i))*CDIM + h*HS + tid] = acc / (float)count;
    }
}

// ---------------------------------------------------------------------------
extern "C" void kernel_launch(void* const* d_in, const int* in_sizes, int n_in,
                              void* d_out, int out_size)
{
    const float* x      = (const float*)d_in[0];
    const float* W_attn = (const float*)d_in[1];
    const float* b_attn = (const float*)d_in[2];
    const float* W_proj = (const float*)d_in[3];
    const float* b_proj = (const float*)d_in[4];
    float* out = (float*)d_out;

    // QKV: [2048,768] @ [768,2304] -> scatter to g_q/g_k/g_v
    {
        dim3 grid(2304/64, 2048/64);
        sgemm_kernel<<<grid, 256>>>(x, W_attn, b_attn, nullptr,
                                    BATCH*SEQ, 3*CDIM, CDIM, 0);
    }
    // DPP attention -> g_y
    {
        dim3 grid(SEQ, BH);
        dpp_kernel<<<grid, 256>>>();
    }
    // Proj: g_y [2048,768] @ [768,768] -> out
    {
        dim3 grid(CDIM/64, 2048/64);
        sgemm_kernel<<<grid, 256>>>(nullptr, W_proj, b_proj, out,
                                    BATCH*SEQ, CDIM, CDIM, 1);
    }
}

// round 2
// speedup vs baseline: 4.5488x; 4.5488x over previous
#include <cuda_runtime.h>
#include <cuda_bf16.h>
#include <math.h>
#include <float.h>

#define BATCH 4
#define SEQ   512
#define CDIM  768
#define NHEAD 12
#define HS    64
#define BH    (BATCH*NHEAD)      // 48
#define WPB   4                  // warps per block in dpp

// Scratch (device globals; allocation is forbidden)
__device__ float g_q[BH*SEQ*HS];      // [b,h,t,d]
__device__ float g_k[BH*SEQ*HS];
__device__ float g_v[BH*SEQ*HS];
__device__ float g_y[BATCH*SEQ*CDIM]; // [b,t,c]

// ---------------------------------------------------------------------------
// Tiled SGEMM: C[M,N] = A[M,K] @ W[K,N] + bias[N]
// mode 0: scatter into g_q/g_k/g_v   mode 1: plain store
// ---------------------------------------------------------------------------
__global__ __launch_bounds__(256)
void sgemm_kernel(const float* __restrict__ A, const float* __restrict__ W,
                  const float* __restrict__ bias, float* __restrict__ Cout,
                  int M, int N, int K, int mode)
{
    __shared__ __align__(16) float As[16][68];
    __shared__ __align__(16) float Bs[16][64];

    const float* Ain = A ? A : g_y;

    int tid = threadIdx.x;
    int bm = blockIdx.y, bn = blockIdx.x;
    int ty = tid >> 4, tx = tid & 15;

    float acc[4][4];
#pragma unroll
    for (int i = 0; i < 4; i++)
#pragma unroll
        for (int j = 0; j < 4; j++) acc[i][j] = 0.f;

    for (int k0 = 0; k0 < K; k0 += 16) {
#pragma unroll
        for (int r = 0; r < 4; r++) {
            int idx = tid + 256*r;
            int row = idx >> 4, col = idx & 15;
            As[col][row] = Ain[(size_t)(bm*64 + row)*K + k0 + col];
        }
#pragma unroll
        for (int r = 0; r < 4; r++) {
            int idx = tid + 256*r;
            int row = idx >> 6, col = idx & 63;
            Bs[row][col] = W[(size_t)(k0 + row)*N + bn*64 + col];
        }
        __syncthreads();
#pragma unroll
        for (int kk = 0; kk < 16; kk++) {
            float4 a4 = *(const float4*)&As[kk][ty*4];
            float4 b4 = *(const float4*)&Bs[kk][tx*4];
            float a[4] = {a4.x, a4.y, a4.z, a4.w};
            float b[4] = {b4.x, b4.y, b4.z, b4.w};
#pragma unroll
            for (int i = 0; i < 4; i++)
#pragma unroll
                for (int j = 0; j < 4; j++) acc[i][j] = fmaf(a[i], b[j], acc[i][j]);
        }
        __syncthreads();
    }

#pragma unroll
    for (int i = 0; i < 4; i++) {
        int row = bm*64 + ty*4 + i;
#pragma unroll
        for (int j = 0; j < 4; j++) {
            int col = bn*64 + tx*4 + j;
            float v = acc[i][j] + bias[col];
            if (mode == 1) {
                Cout[(size_t)row*N + col] = v;
            } else {
                int sect = col / CDIM;          // 0=q 1=k 2=v
                int c = col - sect*CDIM;
                int h = c >> 6;
                int dd = c & 63;
                int bb = row >> 9;              // row = b*512 + t
                int t  = row & 511;
                float* dst = (sect == 0) ? g_q : (sect == 1 ? g_k : g_v);
                dst[(((size_t)(bb*NHEAD + h))*SEQ + t)*HS + dd] = v;
            }
        }
    }
}

// ---------------------------------------------------------------------------
// DPP greedy selection attention. One WARP per (b,h,token). No __syncthreads.
// ---------------------------------------------------------------------------
__global__ __launch_bounds__(32*WPB)
void dpp_kernel()
{
    __shared__ __align__(16) float ssim[WPB][SEQ];
    __shared__ __align__(16) float krows[WPB][17][68];
    __shared__ float Gm[WPB][17][17];

    const unsigned FULL = 0xffffffffu;
    const int lane = threadIdx.x & 31;
    const int wrp  = threadIdx.x >> 5;
    const int i  = blockIdx.x * WPB + wrp;   // token
    const int bh = blockIdx.y;

    const float* __restrict__ kb = g_k + (size_t)bh*SEQ*HS;
    const float* __restrict__ vb = g_v + (size_t)bh*SEQ*HS;
    const float* __restrict__ qi = g_q + ((size_t)bh*SEQ + i)*HS;

    const int half = lane >> 4;   // 0/1 : which row of the pair
    const int hl   = lane & 15;   // chunk within row

    // ---- sim[j] = k[j].q_i, two rows per warp-iteration, fully coalesced ----
    const int nvalid = i + 1;
    float4 qc = ((const float4*)qi)[hl];
    float* sw = ssim[wrp];
    for (int jb = 0; jb < nvalid; jb += 2) {
        int row = jb + half;
        float p = 0.f;
        if (row < nvalid) {
            float4 kv = ((const float4*)(kb + (size_t)row*HS))[hl];
            p = fmaf(kv.x, qc.x, fmaf(kv.y, qc.y, fmaf(kv.z, qc.z, kv.w*qc.w)));
        }
        p += __shfl_xor_sync(FULL, p, 1);
        p += __shfl_xor_sync(FULL, p, 2);
        p += __shfl_xor_sync(FULL, p, 4);
        p += __shfl_xor_sync(FULL, p, 8);
        if (hl == 0 && row < nvalid) sw[row] = p;
    }
    __syncwarp();

    // ---- register-resident top-16 (tie -> lower global index) ----
    float val[16];
#pragma unroll
    for (int c = 0; c < 16; c++) {
        int idx = c*32 + lane;
        val[c] = (idx < nvalid) ? sw[idx] : -INFINITY;
    }
    float myVal = -INFINITY; int myIdx = i;   // lane t (<16) ends owning top-t
    for (int t = 0; t < 16; t++) {
        float bv = val[0]; int bc = 0;
#pragma unroll
        for (int c = 1; c < 16; c++) if (val[c] > bv) { bv = val[c]; bc = c; }
        int bg = bc*32 + lane;
#pragma unroll
        for (int off = 16; off; off >>= 1) {
            float ov = __shfl_down_sync(FULL, bv, off);
            int   og = __shfl_down_sync(FULL, bg, off);
            if (ov > bv || (ov == bv && og < bg)) { bv = ov; bg = og; }
        }
        bv = __shfl_sync(FULL, bv, 0);
        bg = __shfl_sync(FULL, bg, 0);
        if (lane == (bg & 31)) {
            int cc = bg >> 5;
#pragma unroll
            for (int c = 0; c < 16; c++) if (c == cc) val[c] = -INFINITY;
        }
        if (lane == t) { myVal = bv; myIdx = bg; }
    }
    bool availb = (lane < 16) && (myVal > -INFINITY) && (myIdx != i);
    unsigned avail = __ballot_sync(FULL, availb) & 0xFFFFu;
    int safeIdx = (lane < 16 && myVal > -INFINITY) ? myIdx : i;

    // ---- stage 17 k-rows (cand 0..15, then i) into padded smem ----
    for (int r = 0; r < 17; r += 2) {
        int src = r + half;               // 0..17
        int sl  = src & 15;
        int gv  = __shfl_sync(FULL, safeIdx, sl);
        int gidx = (src >= 16) ? i : gv;
        if (src <= 16) {
            float4 kv = ((const float4*)(kb + (size_t)gidx*HS))[hl];
            *(float4*)&krows[wrp][src][hl*4] = kv;
        }
    }
    __syncwarp();

    // ---- 17x17 Gram from smem (symmetric halves) ----
#pragma unroll
    for (int t = 0; t < 10; t++) {
        int e = lane + 32*t;
        if (e < 289) {
            int a = e / 17, b = e - a*17;
            if (a <= b) {
                const float* ra = krows[wrp][a];
                const float* rb = krows[wrp][b];
                float acc = 0.f;
#pragma unroll
                for (int c = 0; c < 16; c++) {
                    float4 x = ((const float4*)ra)[c];
                    float4 y = ((const float4*)rb)[c];
                    acc = fmaf(x.x, y.x, acc);
                    acc = fmaf(x.y, y.y, acc);
                    acc = fmaf(x.z, y.z, acc);
                    acc = fmaf(x.w, y.w, acc);
                }
                Gm[wrp][a][b] = acc;
                Gm[wrp][b][a] = acc;
            }
        }
    }
    __syncwarp();

    // ---- greedy loop with incremental Cholesky (all register/shfl) ----
    const int cl = lane & 15;
    float Gii  = Gm[wrp][16][16];
    float detS = Gii;
    float curS = -logf(Gii + 1e-6f);
    int count = 1;
    float w[8];
    float w0 = Gm[wrp][cl][16] / sqrtf(Gii);
    w[0] = w0;
#pragma unroll
    for (int j = 1; j < 8; j++) w[j] = 0.f;
    float ec = Gm[wrp][cl][cl] - w0*w0;
    int selTok[8];
    selTok[0] = i;
#pragma unroll
    for (int j = 1; j < 8; j++) selTok[j] = i;

    for (int step = 0; step < 7; step++) {
        bool av = (lane < 16) && ((avail >> lane) & 1u);
        float s = av ? (-logf(detS*ec + 1e-6f) / (float)(count + 1)) : -INFINITY;
        // NaN-aware argmax over candidate slots (first index wins; NaN is max)
        float bs = s; int bl = lane;
#pragma unroll
        for (int off = 16; off; off >>= 1) {
            float ov = __shfl_down_sync(FULL, bs, off);
            int   ol = __shfl_down_sync(FULL, bl, off);
            bool nb = isnan(bs), no = isnan(ov);
            bool better = (!nb && (no || ov > bs)) ||
                          (((nb && no) || (ov == bs)) && ol < bl);
            if (better) { bs = ov; bl = ol; }
        }
        bs = __shfl_sync(FULL, bs, 0);
        bl = __shfl_sync(FULL, bl, 0);
        bool anyAvail = (avail != 0u);
        bool accept = anyAvail && ((bs > curS) || (count < 2));
        if (!accept) break;   // warp-uniform

        float eb = __shfl_sync(FULL, ec, bl);
        float Lb = sqrtf(eb);
        float dot = 0.f;
#pragma unroll
        for (int j = 0; j < 7; j++) {
            float wbj = __shfl_sync(FULL, w[j], bl);
            if (j < count) dot += w[j]*wbj;
        }
        float wn = (Gm[wrp][cl][bl] - dot) / Lb;
#pragma unroll
        for (int j = 1; j < 8; j++) if (j == count) w[j] = wn;
        ec -= wn*wn;
        detS *= eb;
        curS = bs;
        int btok = __shfl_sync(FULL, myIdx, bl);
#pragma unroll
        for (int j = 1; j < 8; j++) if (j == count) selTok[j] = btok;
        count++;
        avail &= ~(1u << bl);
    }

    // ---- y_i = mean of selected v rows ----
    float a0 = 0.f, a1 = 0.f;
#pragma unroll
    for (int r = 0; r < 8; r++) {
        if (r < count) {
            const float* vr = vb + (size_t)selTok[r]*HS;
            a0 += vr[lane];
            a1 += vr[lane + 32];
        }
    }
    float cnt = (float)count;
    int bb = bh / NHEAD, h = bh % NHEAD;
    float* yo = g_y + ((size_t)(bb*SEQ + i))*CDIM + h*HS;
    yo[lane]      = a0 / cnt;
    yo[lane + 32] = a1 / cnt;
}

// ---------------------------------------------------------------------------
extern "C" void kernel_launch(void* const* d_in, const int* in_sizes, int n_in,
                              void* d_out, int out_size)
{
    const float* x      = (const float*)d_in[0];
    const float* W_attn = (const float*)d_in[1];
    const float* b_attn = (const float*)d_in[2];
    const float* W_proj = (const float*)d_in[3];
    const float* b_proj = (const float*)d_in[4];
    float* out = (float*)d_out;

    {   // QKV: [2048,768] @ [768,2304] -> scatter to g_q/g_k/g_v
        dim3 grid(2304/64, 2048/64);
        sgemm_kernel<<<grid, 256>>>(x, W_attn, b_attn, nullptr,
                                    BATCH*SEQ, 3*CDIM, CDIM, 0);
    }
    {   // DPP attention -> g_y  (one warp per token)
        dim3 grid(SEQ/WPB, BH);
        dpp_kernel<<<grid, 32*WPB>>>();
    }
    {   // Proj: g_y [2048,768] @ [768,768] -> out
        dim3 grid(CDIM/64, 2048/64);
        sgemm_kernel<<<grid, 256>>>(nullptr, W_proj, b_proj, out,
                                    BATCH*SEQ, CDIM, CDIM, 1);
    }
}

// round 3
// speedup vs baseline: 5.3253x; 1.1707x over previous
#include <cuda_runtime.h>
#include <cuda_bf16.h>
#include <math.h>
#include <float.h>

#define BATCH 4
#define SEQ   512
#define CDIM  768
#define NHEAD 12
#define HS    64
#define BH    (BATCH*NHEAD)      // 48
#define DW    8                  // warps (tokens) per dpp block

// Scratch (device globals; allocation is forbidden)
__device__ float g_q [BH*SEQ*HS];      // [b,h,t,d]
__device__ float g_k [BH*SEQ*HS];      // [b,h,t,d]
__device__ float g_kT[BH*HS*SEQ];      // [b,h,d,t]  (transposed copy for sim)
__device__ float g_v [BH*SEQ*HS];
__device__ float g_y [BATCH*SEQ*CDIM]; // [b,t,c]

// ---------------------------------------------------------------------------
// 128x128 tiled SGEMM, 8x8 micro-tile, register-prefetch pipeline.
// C[M,N] = A[M,K] @ W[K,N] + bias[N]
// mode 0: scatter into g_q/g_k/g_kT/g_v    mode 1: plain store
// Requires M%128==0, N%128==0, K%16==0.
// ---------------------------------------------------------------------------
__global__ __launch_bounds__(256)
void sgemm_kernel(const float* __restrict__ A, const float* __restrict__ W,
                  const float* __restrict__ bias, float* __restrict__ Cout,
                  int M, int N, int K, int mode)
{
    __shared__ __align__(16) float As[16][132];   // [k][m], padded
    __shared__ __align__(16) float Bs[16][128];   // [k][n]

    const float* Ain = A ? A : g_y;

    const int tid = threadIdx.x;
    const int bm = blockIdx.y, bn = blockIdx.x;
    const int ty = tid >> 4, tx = tid & 15;       // 16x16 thread grid

    // loader coords
    const int ar = tid >> 2;            // 0..63  (A rows, two groups: ar, ar+64)
    const int ac = (tid & 3) * 4;       // 0,4,8,12 (A k-cols, float4)
    const int br = tid >> 5;            // 0..7   (B k-rows, two groups: br, br+8)
    const int bc = (tid & 31) * 4;      // 0..124 (B n-cols, float4)

    float acc[8][8];
#pragma unroll
    for (int i = 0; i < 8; i++)
#pragma unroll
        for (int j = 0; j < 8; j++) acc[i][j] = 0.f;

    float4 pa0, pa1, pb0, pb1;
    // initial prefetch (k0 = 0)
    pa0 = *(const float4*)&Ain[(size_t)(bm*128 + ar     )*K + ac];
    pa1 = *(const float4*)&Ain[(size_t)(bm*128 + ar + 64)*K + ac];
    pb0 = *(const float4*)&W  [(size_t)(br     )*N + bn*128 + bc];
    pb1 = *(const float4*)&W  [(size_t)(br +  8)*N + bn*128 + bc];

    for (int k0 = 0; k0 < K; k0 += 16) {
        // store staged tile to smem (A transposed)
        As[ac+0][ar]      = pa0.x; As[ac+1][ar]      = pa0.y;
        As[ac+2][ar]      = pa0.z; As[ac+3][ar]      = pa0.w;
        As[ac+0][ar+64]   = pa1.x; As[ac+1][ar+64]   = pa1.y;
        As[ac+2][ar+64]   = pa1.z; As[ac+3][ar+64]   = pa1.w;
        *(float4*)&Bs[br  ][bc] = pb0;
        *(float4*)&Bs[br+8][bc] = pb1;
        __syncthreads();

        if (k0 + 16 < K) {
            pa0 = *(const float4*)&Ain[(size_t)(bm*128 + ar     )*K + k0 + 16 + ac];
            pa1 = *(const float4*)&Ain[(size_t)(bm*128 + ar + 64)*K + k0 + 16 + ac];
            pb0 = *(const float4*)&W  [(size_t)(k0 + 16 + br    )*N + bn*128 + bc];
            pb1 = *(const float4*)&W  [(size_t)(k0 + 16 + br + 8)*N + bn*128 + bc];
        }

#pragma unroll
        for (int kk = 0; kk < 16; kk++) {
            float4 a0 = *(const float4*)&As[kk][ty*8];
            float4 a1 = *(const float4*)&As[kk][ty*8 + 4];
            float4 b0 = *(const float4*)&Bs[kk][tx*8];
            float4 b1 = *(const float4*)&Bs[kk][tx*8 + 4];
            float a[8] = {a0.x,a0.y,a0.z,a0.w,a1.x,a1.y,a1.z,a1.w};
            float b[8] = {b0.x,b0.y,b0.z,b0.w,b1.x,b1.y,b1.z,b1.w};
#pragma unroll
            for (int i = 0; i < 8; i++)
#pragma unroll
                for (int j = 0; j < 8; j++) acc[i][j] = fmaf(a[i], b[j], acc[i][j]);
        }
        __syncthreads();
    }

#pragma unroll
    for (int i = 0; i < 8; i++) {
        int row = bm*128 + ty*8 + i;
#pragma unroll
        for (int j = 0; j < 8; j++) {
            int col = bn*128 + tx*8 + j;
            float v = acc[i][j] + bias[col];
            if (mode == 1) {
                Cout[(size_t)row*N + col] = v;
            } else {
                int sect = col / CDIM;          // 0=q 1=k 2=v
                int c = col - sect*CDIM;
                int h = c >> 6;
                int dd = c & 63;
                int bb = row >> 9;              // row = b*512 + t
                int t  = row & 511;
                int bhh = bb*NHEAD + h;
                size_t off = (((size_t)bhh)*SEQ + t)*HS + dd;
                if (sect == 0) g_q[off] = v;
                else if (sect == 2) g_v[off] = v;
                else {
                    g_k[off] = v;
                    g_kT[((size_t)bhh*HS + dd)*SEQ + t] = v;
                }
            }
        }
    }
}

// ---------------------------------------------------------------------------
// DPP greedy selection attention. One WARP per (b,h,token), DW warps/block
// over consecutive tokens of the same head (kT prefix shared via L1).
// ---------------------------------------------------------------------------
__global__ __launch_bounds__(32*DW)
void dpp_kernel()
{
    __shared__ __align__(16) float sq[DW][64];
    __shared__ __align__(16) float krows[DW][17][68];
    __shared__ float Gm[DW][17][17];

    const unsigned FULL = 0xffffffffu;
    const int lane = threadIdx.x & 31;
    const int wrp  = threadIdx.x >> 5;
    const int i  = blockIdx.x * DW + wrp;   // token
    const int bh = blockIdx.y;
    const int nvalid = i + 1;

    const float* __restrict__ kb  = g_k  + (size_t)bh*SEQ*HS;
    const float* __restrict__ kT  = g_kT + (size_t)bh*HS*SEQ;
    const float* __restrict__ vb  = g_v  + (size_t)bh*SEQ*HS;
    const float* __restrict__ qi  = g_q  + ((size_t)bh*SEQ + i)*HS;

    sq[wrp][lane]      = qi[lane];
    sq[wrp][lane + 32] = qi[lane + 32];
    __syncwarp();

    // ---- sim: lane owns rows 128c + 4*lane + (0..3); no shuffles ----
    float val[16];
#pragma unroll
    for (int c = 0; c < 4; c++) {
        int base = 128*c;
        float4 acc = make_float4(0.f, 0.f, 0.f, 0.f);
        if (base < nvalid) {
            const float* kp = kT + base + 4*lane;
#pragma unroll
            for (int d = 0; d < 64; d++) {
                float qd = sq[wrp][d];
                float4 kv = *(const float4*)(kp + (size_t)d*SEQ);
                acc.x = fmaf(kv.x, qd, acc.x);
                acc.y = fmaf(kv.y, qd, acc.y);
                acc.z = fmaf(kv.z, qd, acc.z);
                acc.w = fmaf(kv.w, qd, acc.w);
            }
        }
        int rb = base + 4*lane;
        val[4*c+0] = (rb + 0 < nvalid) ? acc.x : -INFINITY;
        val[4*c+1] = (rb + 1 < nvalid) ? acc.y : -INFINITY;
        val[4*c+2] = (rb + 2 < nvalid) ? acc.z : -INFINITY;
        val[4*c+3] = (rb + 3 < nvalid) ? acc.w : -INFINITY;
    }

    // ---- register-resident top-16 (tie -> lower global index) ----
    float myVal = -INFINITY; int myIdx = i;   // lane t (<16) ends owning top-t
    for (int t = 0; t < 16; t++) {
        float bv = val[0]; int bc = 0;
#pragma unroll
        for (int c = 1; c < 16; c++) if (val[c] > bv) { bv = val[c]; bc = c; }
        int bg = 128*(bc >> 2) + 4*lane + (bc & 3);
#pragma unroll
        for (int off = 16; off; off >>= 1) {
            float ov = __shfl_down_sync(FULL, bv, off);
            int   og = __shfl_down_sync(FULL, bg, off);
            if (ov > bv || (ov == bv && og < bg)) { bv = ov; bg = og; }
        }
        bv = __shfl_sync(FULL, bv, 0);
        bg = __shfl_sync(FULL, bg, 0);
        if (((bg >> 2) & 31) == lane) {
            int cc = ((bg >> 7) << 2) | (bg & 3);
#pragma unroll
            for (int c = 0; c < 16; c++) if (c == cc) val[c] = -INFINITY;
        }
        if (lane == t) { myVal = bv; myIdx = bg; }
    }
    bool availb = (lane < 16) && (myVal > -INFINITY) && (myIdx != i);
    unsigned avail = __ballot_sync(FULL, availb) & 0xFFFFu;
    int safeIdx = (lane < 16 && myVal > -INFINITY) ? myIdx : i;

    // ---- stage 17 k-rows (cand 0..15, then i) into padded smem ----
    const int half = lane >> 4;
    const int hl   = lane & 15;
    for (int r = 0; r < 17; r += 2) {
        int src = r + half;               // 0..17
        int sl  = src & 15;
        int gv  = __shfl_sync(FULL, safeIdx, sl);
        int gidx = (src >= 16) ? i : gv;
        if (src <= 16) {
            float4 kv = ((const float4*)(kb + (size_t)gidx*HS))[hl];
            *(float4*)&krows[wrp][src][hl*4] = kv;
        }
    }
    __syncwarp();

    // ---- 17x17 Gram from smem (symmetric halves) ----
#pragma unroll
    for (int t = 0; t < 10; t++) {
        int e = lane + 32*t;
        if (e < 289) {
            int a = e / 17, b = e - a*17;
            if (a <= b) {
                const float* ra = krows[wrp][a];
                const float* rb = krows[wrp][b];
                float acc = 0.f;
#pragma unroll
                for (int c = 0; c < 16; c++) {
                    float4 x = ((const float4*)ra)[c];
                    float4 y = ((const float4*)rb)[c];
                    acc = fmaf(x.x, y.x, acc);
                    acc = fmaf(x.y, y.y, acc);
                    acc = fmaf(x.z, y.z, acc);
                    acc = fmaf(x.w, y.w, acc);
                }
                Gm[wrp][a][b] = acc;
                Gm[wrp][b][a] = acc;
            }
        }
    }
    __syncwarp();

    // ---- greedy loop with incremental Cholesky (all register/shfl) ----
    const int cl = lane & 15;
    float Gii  = Gm[wrp][16][16];
    float detS = Gii;
    float curS = -logf(Gii + 1e-6f);
    int count = 1;
    float w[8];
    float w0 = Gm[wrp][cl][16] / sqrtf(Gii);
    w[0] = w0;
#pragma unroll
    for (int j = 1; j < 8; j++) w[j] = 0.f;
    float ec = Gm[wrp][cl][cl] - w0*w0;
    int selTok[8];
#pragma unroll
    for (int j = 0; j < 8; j++) selTok[j] = i;

    for (int step = 0; step < 7; step++) {
        bool av = (lane < 16) && ((avail >> lane) & 1u);
        float s = av ? (-logf(detS*ec + 1e-6f) / (float)(count + 1)) : -INFINITY;
        // NaN-aware argmax over candidate slots (first index wins; NaN is max)
        float bs = s; int bl = lane;
#pragma unroll
        for (int off = 16; off; off >>= 1) {
            float ov = __shfl_down_sync(FULL, bs, off);
            int   ol = __shfl_down_sync(FULL, bl, off);
            bool nb = isnan(bs), no = isnan(ov);
            bool better = (!nb && (no || ov > bs)) ||
                          (((nb && no) || (ov == bs)) && ol < bl);
            if (better) { bs = ov; bl = ol; }
        }
        bs = __shfl_sync(FULL, bs, 0);
        bl = __shfl_sync(FULL, bl, 0);
        bool anyAvail = (avail != 0u);
        bool accept = anyAvail && ((bs > curS) || (count < 2));
        if (!accept) break;   // warp-uniform

        float eb = __shfl_sync(FULL, ec, bl);
        float Lb = sqrtf(eb);
        float dot = 0.f;
#pragma unroll
        for (int j = 0; j < 7; j++) {
            float wbj = __shfl_sync(FULL, w[j], bl);
            if (j < count) dot += w[j]*wbj;
        }
        float wn = (Gm[wrp][cl][bl] - dot) / Lb;
#pragma unroll
        for (int j = 1; j < 8; j++) if (j == count) w[j] = wn;
        ec -= wn*wn;
        detS *= eb;
        curS = bs;
        int btok = __shfl_sync(FULL, myIdx, bl);
#pragma unroll
        for (int j = 1; j < 8; j++) if (j == count) selTok[j] = btok;
        count++;
        avail &= ~(1u << bl);
    }

    // ---- y_i = mean of selected v rows ----
    float a0 = 0.f, a1 = 0.f;
#pragma unroll
    for (int r = 0; r < 8; r++) {
        if (r < count) {
            const float* vr = vb + (size_t)selTok[r]*HS;
            a0 += vr[lane];
            a1 += vr[lane + 32];
        }
    }
    float cnt = (float)count;
    int bb = bh / NHEAD, h = bh % NHEAD;
    float* yo = g_y + ((size_t)(bb*SEQ + i))*CDIM + h*HS;
    yo[lane]      = a0 / cnt;
    yo[lane + 32] = a1 / cnt;
}

// ---------------------------------------------------------------------------
extern "C" void kernel_launch(void* const* d_in, const int* in_sizes, int n_in,
                              void* d_out, int out_size)
{
    const float* x      = (const float*)d_in[0];
    const float* W_attn = (const float*)d_in[1];
    const float* b_attn = (const float*)d_in[2];
    const float* W_proj = (const float*)d_in[3];
    const float* b_proj = (const float*)d_in[4];
    float* out = (float*)d_out;

    {   // QKV: [2048,768] @ [768,2304] -> scatter to g_q/g_k/g_kT/g_v
        dim3 grid(2304/128, 2048/128);
        sgemm_kernel<<<grid, 256>>>(x, W_attn, b_attn, nullptr,
                                    BATCH*SEQ, 3*CDIM, CDIM, 0);
    }
    {   // DPP attention -> g_y  (one warp per token, 8 tokens per block)
        dim3 grid(SEQ/DW, BH);
        dpp_kernel<<<grid, 32*DW>>>();
    }
    {   // Proj: g_y [2048,768] @ [768,768] -> out
        dim3 grid(CDIM/128, 2048/128);
        sgemm_kernel<<<grid, 256>>>(nullptr, W_proj, b_proj, out,
                                    BATCH*SEQ, CDIM, CDIM, 1);
    }
}

// round 4
// speedup vs baseline: 5.8529x; 1.0991x over previous
#include <cuda_runtime.h>
#include <cuda_bf16.h>
#include <math.h>
#include <float.h>

#define BATCH 4
#define SEQ   512
#define CDIM  768
#define NHEAD 12
#define HS    64
#define BH    (BATCH*NHEAD)      // 48
#define DW    8                  // warps (tokens) per dpp block

// Scratch (device globals; allocation is forbidden)
__device__ float g_q  [BH*SEQ*HS];       // [b,h,t,d]
__device__ float g_k  [BH*SEQ*HS];       // [b,h,t,d]
__device__ float g_v  [BH*SEQ*HS];
__device__ float g_sim[(size_t)BH*SEQ*SEQ]; // [b,h,i,j] q_i . k_j
__device__ float g_y  [BATCH*SEQ*CDIM];  // [b,t,c]

// ---------------------------------------------------------------------------
// 128x128 tiled SGEMM, 8x8 micro-tile, double-buffered smem.
// C[M,N] = A[M,K] @ W[K,N] + bias[N]
// mode 0: scatter into g_q/g_k/g_v    mode 1: plain store
// ---------------------------------------------------------------------------
__global__ __launch_bounds__(256)
void sgemm_kernel(const float* __restrict__ A, const float* __restrict__ W,
                  const float* __restrict__ bias, float* __restrict__ Cout,
                  int M, int N, int K, int mode)
{
    __shared__ __align__(16) float As[2][16][132];   // [buf][k][m]
    __shared__ __align__(16) float Bs[2][16][128];   // [buf][k][n]

    const float* Ain = A ? A : g_y;

    const int tid = threadIdx.x;
    const int bm = blockIdx.y, bn = blockIdx.x;
    const int ty = tid >> 4, tx = tid & 15;

    const int ar = tid >> 2;            // 0..63
    const int ac = (tid & 3) * 4;       // 0,4,8,12
    const int br = tid >> 5;            // 0..7
    const int bc = (tid & 31) * 4;      // 0..124

    float acc[8][8];
#pragma unroll
    for (int i = 0; i < 8; i++)
#pragma unroll
        for (int j = 0; j < 8; j++) acc[i][j] = 0.f;

    float4 pa0, pa1, pb0, pb1;
    pa0 = *(const float4*)&Ain[(size_t)(bm*128 + ar     )*K + ac];
    pa1 = *(const float4*)&Ain[(size_t)(bm*128 + ar + 64)*K + ac];
    pb0 = *(const float4*)&W  [(size_t)(br     )*N + bn*128 + bc];
    pb1 = *(const float4*)&W  [(size_t)(br +  8)*N + bn*128 + bc];

    // store first tile into buf 0
    As[0][ac+0][ar]    = pa0.x; As[0][ac+1][ar]    = pa0.y;
    As[0][ac+2][ar]    = pa0.z; As[0][ac+3][ar]    = pa0.w;
    As[0][ac+0][ar+64] = pa1.x; As[0][ac+1][ar+64] = pa1.y;
    As[0][ac+2][ar+64] = pa1.z; As[0][ac+3][ar+64] = pa1.w;
    *(float4*)&Bs[0][br  ][bc] = pb0;
    *(float4*)&Bs[0][br+8][bc] = pb1;

    int cur = 0;
    for (int k0 = 0; k0 < K; k0 += 16) {
        __syncthreads();
        bool more = (k0 + 16 < K);
        if (more) {
            pa0 = *(const float4*)&Ain[(size_t)(bm*128 + ar     )*K + k0 + 16 + ac];
            pa1 = *(const float4*)&Ain[(size_t)(bm*128 + ar + 64)*K + k0 + 16 + ac];
            pb0 = *(const float4*)&W  [(size_t)(k0 + 16 + br    )*N + bn*128 + bc];
            pb1 = *(const float4*)&W  [(size_t)(k0 + 16 + br + 8)*N + bn*128 + bc];
        }
#pragma unroll
        for (int kk = 0; kk < 16; kk++) {
            float4 a0 = *(const float4*)&As[cur][kk][ty*8];
            float4 a1 = *(const float4*)&As[cur][kk][ty*8 + 4];
            float4 b0 = *(const float4*)&Bs[cur][kk][tx*8];
            float4 b1 = *(const float4*)&Bs[cur][kk][tx*8 + 4];
            float a[8] = {a0.x,a0.y,a0.z,a0.w,a1.x,a1.y,a1.z,a1.w};
            float b[8] = {b0.x,b0.y,b0.z,b0.w,b1.x,b1.y,b1.z,b1.w};
#pragma unroll
            for (int i = 0; i < 8; i++)
#pragma unroll
                for (int j = 0; j < 8; j++) acc[i][j] = fmaf(a[i], b[j], acc[i][j]);
        }
        if (more) {
            int nxt = cur ^ 1;
            As[nxt][ac+0][ar]    = pa0.x; As[nxt][ac+1][ar]    = pa0.y;
            As[nxt][ac+2][ar]    = pa0.z; As[nxt][ac+3][ar]    = pa0.w;
            As[nxt][ac+0][ar+64] = pa1.x; As[nxt][ac+1][ar+64] = pa1.y;
            As[nxt][ac+2][ar+64] = pa1.z; As[nxt][ac+3][ar+64] = pa1.w;
            *(float4*)&Bs[nxt][br  ][bc] = pb0;
            *(float4*)&Bs[nxt][br+8][bc] = pb1;
        }
        cur ^= 1;
    }

#pragma unroll
    for (int i = 0; i < 8; i++) {
        int row = bm*128 + ty*8 + i;
#pragma unroll
        for (int j = 0; j < 8; j++) {
            int col = bn*128 + tx*8 + j;
            float v = acc[i][j] + bias[col];
            if (mode == 1) {
                Cout[(size_t)row*N + col] = v;
            } else {
                int sect = col / CDIM;          // 0=q 1=k 2=v
                int c = col - sect*CDIM;
                int h = c >> 6;
                int dd = c & 63;
                int bb = row >> 9;
                int t  = row & 511;
                int bhh = bb*NHEAD + h;
                size_t off = (((size_t)bhh)*SEQ + t)*HS + dd;
                float* dst = (sect == 0) ? g_q : (sect == 1 ? g_k : g_v);
                dst[off] = v;
            }
        }
    }
}

// ---------------------------------------------------------------------------
// Sim GEMM: S[bh][i][j] = q_i . k_j  per head, lower-triangular blocks only.
// 128x128 tile, 8x8 micro, K=64.
// ---------------------------------------------------------------------------
__global__ __launch_bounds__(256)
void simgemm_kernel()
{
    const int bm = blockIdx.y, bn = blockIdx.x;
    if (bn > bm) return;                       // causal: only j-block <= i-block
    const int bh = blockIdx.z;

    __shared__ __align__(16) float As[16][132]; // [d][i]
    __shared__ __align__(16) float Bs[16][132]; // [d][j]

    const float* __restrict__ qb = g_q + (size_t)bh*SEQ*HS;
    const float* __restrict__ kb = g_k + (size_t)bh*SEQ*HS;

    const int tid = threadIdx.x;
    const int ty = tid >> 4, tx = tid & 15;
    const int rr = tid >> 2;              // 0..63
    const int rc = (tid & 3) * 4;         // 0,4,8,12

    float acc[8][8];
#pragma unroll
    for (int i = 0; i < 8; i++)
#pragma unroll
        for (int j = 0; j < 8; j++) acc[i][j] = 0.f;

    for (int d0 = 0; d0 < HS; d0 += 16) {
        // load q tile [128 rows][16 d] transposed -> As[d][i]
        float4 qa0 = *(const float4*)&qb[(size_t)(bm*128 + rr     )*HS + d0 + rc];
        float4 qa1 = *(const float4*)&qb[(size_t)(bm*128 + rr + 64)*HS + d0 + rc];
        float4 ka0 = *(const float4*)&kb[(size_t)(bn*128 + rr     )*HS + d0 + rc];
        float4 ka1 = *(const float4*)&kb[(size_t)(bn*128 + rr + 64)*HS + d0 + rc];
        As[rc+0][rr]    = qa0.x; As[rc+1][rr]    = qa0.y;
        As[rc+2][rr]    = qa0.z; As[rc+3][rr]    = qa0.w;
        As[rc+0][rr+64] = qa1.x; As[rc+1][rr+64] = qa1.y;
        As[rc+2][rr+64] = qa1.z; As[rc+3][rr+64] = qa1.w;
        Bs[rc+0][rr]    = ka0.x; Bs[rc+1][rr]    = ka0.y;
        Bs[rc+2][rr]    = ka0.z; Bs[rc+3][rr]    = ka0.w;
        Bs[rc+0][rr+64] = ka1.x; Bs[rc+1][rr+64] = ka1.y;
        Bs[rc+2][rr+64] = ka1.z; Bs[rc+3][rr+64] = ka1.w;
        __syncthreads();
#pragma unroll
        for (int kk = 0; kk < 16; kk++) {
            float4 a0 = *(const float4*)&As[kk][ty*8];
            float4 a1 = *(const float4*)&As[kk][ty*8 + 4];
            float4 b0 = *(const float4*)&Bs[kk][tx*8];
            float4 b1 = *(const float4*)&Bs[kk][tx*8 + 4];
            float a[8] = {a0.x,a0.y,a0.z,a0.w,a1.x,a1.y,a1.z,a1.w};
            float b[8] = {b0.x,b0.y,b0.z,b0.w,b1.x,b1.y,b1.z,b1.w};
#pragma unroll
            for (int i = 0; i < 8; i++)
#pragma unroll
                for (int j = 0; j < 8; j++) acc[i][j] = fmaf(a[i], b[j], acc[i][j]);
        }
        __syncthreads();
    }

    float* S = g_sim + (size_t)bh*SEQ*SEQ;
#pragma unroll
    for (int i = 0; i < 8; i++) {
        int row = bm*128 + ty*8 + i;
#pragma unroll
        for (int j = 0; j < 8; j += 4) {
            int col = bn*128 + tx*8 + j;
            float4 v = make_float4(acc[i][j], acc[i][j+1], acc[i][j+2], acc[i][j+3]);
            *(float4*)&S[(size_t)row*SEQ + col] = v;
        }
    }
}

// ---------------------------------------------------------------------------
// DPP greedy selection attention. One WARP per (b,h,token).
// Sim row is precomputed in g_sim.
// ---------------------------------------------------------------------------
__global__ __launch_bounds__(32*DW)
void dpp_kernel()
{
    __shared__ __align__(16) float krows[DW][17][68];
    __shared__ float Gm[DW][17][17];

    const unsigned FULL = 0xffffffffu;
    const int lane = threadIdx.x & 31;
    const int wrp  = threadIdx.x >> 5;
    const int i  = blockIdx.x * DW + wrp;   // token
    const int bh = blockIdx.y;
    const int nvalid = i + 1;

    const float* __restrict__ kb = g_k + (size_t)bh*SEQ*HS;
    const float* __restrict__ vb = g_v + (size_t)bh*SEQ*HS;
    const float* __restrict__ simRow = g_sim + ((size_t)bh*SEQ + i)*SEQ;

    // ---- load sim row: val[c] holds sim[c*32+lane] ----
    float val[16];
#pragma unroll
    for (int c = 0; c < 16; c++) {
        int idx = c*32 + lane;
        val[c] = (idx < nvalid) ? simRow[idx] : -INFINITY;
    }

    // ---- register-resident top-16 (tie -> lower global index) ----
    float myVal = -INFINITY; int myIdx = i;   // lane t (<16) ends owning top-t
    for (int t = 0; t < 16; t++) {
        float bv = val[0]; int bc = 0;
#pragma unroll
        for (int c = 1; c < 16; c++) if (val[c] > bv) { bv = val[c]; bc = c; }
        int bg = bc*32 + lane;
#pragma unroll
        for (int off = 16; off; off >>= 1) {
            float ov = __shfl_down_sync(FULL, bv, off);
            int   og = __shfl_down_sync(FULL, bg, off);
            if (ov > bv || (ov == bv && og < bg)) { bv = ov; bg = og; }
        }
        bv = __shfl_sync(FULL, bv, 0);
        bg = __shfl_sync(FULL, bg, 0);
        if (lane == (bg & 31)) {
            int cc = bg >> 5;
#pragma unroll
            for (int c = 0; c < 16; c++) if (c == cc) val[c] = -INFINITY;
        }
        if (lane == t) { myVal = bv; myIdx = bg; }
    }
    bool availb = (lane < 16) && (myVal > -INFINITY) && (myIdx != i);
    unsigned avail = __ballot_sync(FULL, availb) & 0xFFFFu;
    int safeIdx = (lane < 16 && myVal > -INFINITY) ? myIdx : i;

    // ---- stage 17 k-rows (cand 0..15, then i) into padded smem ----
    const int half = lane >> 4;
    const int hl   = lane & 15;
    for (int r = 0; r < 17; r += 2) {
        int src = r + half;               // 0..17
        int sl  = src & 15;
        int gv  = __shfl_sync(FULL, safeIdx, sl);
        int gidx = (src >= 16) ? i : gv;
        if (src <= 16) {
            float4 kv = ((const float4*)(kb + (size_t)gidx*HS))[hl];
            *(float4*)&krows[wrp][src][hl*4] = kv;
        }
    }
    __syncwarp();

    // ---- 17x17 Gram from smem (symmetric halves) ----
#pragma unroll
    for (int t = 0; t < 10; t++) {
        int e = lane + 32*t;
        if (e < 289) {
            int a = e / 17, b = e - a*17;
            if (a <= b) {
                const float* ra = krows[wrp][a];
                const float* rb = krows[wrp][b];
                float acc = 0.f;
#pragma unroll
                for (int c = 0; c < 16; c++) {
                    float4 x = ((const float4*)ra)[c];
                    float4 y = ((const float4*)rb)[c];
                    acc = fmaf(x.x, y.x, acc);
                    acc = fmaf(x.y, y.y, acc);
                    acc = fmaf(x.z, y.z, acc);
                    acc = fmaf(x.w, y.w, acc);
                }
                Gm[wrp][a][b] = acc;
                Gm[wrp][b][a] = acc;
            }
        }
    }
    __syncwarp();

    // ---- greedy loop with incremental Cholesky (all register/shfl) ----
    const int cl = lane & 15;
    float Gii  = Gm[wrp][16][16];
    float detS = Gii;
    float curS = -logf(Gii + 1e-6f);
    int count = 1;
    float w[8];
    float w0 = Gm[wrp][cl][16] / sqrtf(Gii);
    w[0] = w0;
#pragma unroll
    for (int j = 1; j < 8; j++) w[j] = 0.f;
    float ec = Gm[wrp][cl][cl] - w0*w0;
    int selTok[8];
#pragma unroll
    for (int j = 0; j < 8; j++) selTok[j] = i;

    for (int step = 0; step < 7; step++) {
        bool av = (lane < 16) && ((avail >> lane) & 1u);
        float s = av ? (-logf(detS*ec + 1e-6f) / (float)(count + 1)) : -INFINITY;
        // NaN-aware argmax over candidate slots (first index wins; NaN is max)
        float bs = s; int bl = lane;
#pragma unroll
        for (int off = 16; off; off >>= 1) {
            float ov = __shfl_down_sync(FULL, bs, off);
            int   ol = __shfl_down_sync(FULL, bl, off);
            bool nb = isnan(bs), no = isnan(ov);
            bool better = (!nb && (no || ov > bs)) ||
                          (((nb && no) || (ov == bs)) && ol < bl);
            if (better) { bs = ov; bl = ol; }
        }
        bs = __shfl_sync(FULL, bs, 0);
        bl = __shfl_sync(FULL, bl, 0);
        bool anyAvail = (avail != 0u);
        bool accept = anyAvail && ((bs > curS) || (count < 2));
        if (!accept) break;   // warp-uniform

        float eb = __shfl_sync(FULL, ec, bl);
        float Lb = sqrtf(eb);
        float dot = 0.f;
#pragma unroll
        for (int j = 0; j < 7; j++) {
            float wbj = __shfl_sync(FULL, w[j], bl);
            if (j < count) dot += w[j]*wbj;
        }
        float wn = (Gm[wrp][cl][bl] - dot) / Lb;
#pragma unroll
        for (int j = 1; j < 8; j++) if (j == count) w[j] = wn;
        ec -= wn*wn;
        detS *= eb;
        curS = bs;
        int btok = __shfl_sync(FULL, myIdx, bl);
#pragma unroll
        for (int j = 1; j < 8; j++) if (j == count) selTok[j] = btok;
        count++;
        avail &= ~(1u << bl);
    }

    // ---- y_i = mean of selected v rows ----
    float a0 = 0.f, a1 = 0.f;
#pragma unroll
    for (int r = 0; r < 8; r++) {
        if (r < count) {
            const float* vr = vb + (size_t)selTok[r]*HS;
            a0 += vr[lane];
            a1 += vr[lane + 32];
        }
    }
    float cnt = (float)count;
    int bb = bh / NHEAD, h = bh % NHEAD;
    float* yo = g_y + ((size_t)(bb*SEQ + i))*CDIM + h*HS;
    yo[lane]      = a0 / cnt;
    yo[lane + 32] = a1 / cnt;
}

// ---------------------------------------------------------------------------
extern "C" void kernel_launch(void* const* d_in, const int* in_sizes, int n_in,
                              void* d_out, int out_size)
{
    const float* x      = (const float*)d_in[0];
    const float* W_attn = (const float*)d_in[1];
    const float* b_attn = (const float*)d_in[2];
    const float* W_proj = (const float*)d_in[3];
    const float* b_proj = (const float*)d_in[4];
    float* out = (float*)d_out;

    {   // QKV: [2048,768] @ [768,2304] -> scatter to g_q/g_k/g_v
        dim3 grid(2304/128, 2048/128);
        sgemm_kernel<<<grid, 256>>>(x, W_attn, b_attn, nullptr,
                                    BATCH*SEQ, 3*CDIM, CDIM, 0);
    }
    {   // sim: S = Q K^T per head (lower-triangular blocks)
        dim3 grid(4, 4, BH);
        simgemm_kernel<<<grid, 256>>>();
    }
    {   // DPP attention -> g_y  (one warp per token)
        dim3 grid(SEQ/DW, BH);
        dpp_kernel<<<grid, 32*DW>>>();
    }
    {   // Proj: g_y [2048,768] @ [768,768] -> out
        dim3 grid(CDIM/128, 2048/128);
        sgemm_kernel<<<grid, 256>>>(nullptr, W_proj, b_proj, out,
                                    BATCH*SEQ, CDIM, CDIM, 1);
    }
}

// round 6
// speedup vs baseline: 5.8551x; 1.0004x over previous
#include <cuda_runtime.h>
#include <cuda_bf16.h>
#include <math.h>
#include <float.h>

#define BATCH 4
#define SEQ   512
#define CDIM  768
#define NHEAD 12
#define HS    64
#define BH    (BATCH*NHEAD)      // 48
#define DW    8                  // warps (tokens) per dpp block

// ---------------- device scratch (allocation forbidden) ----------------
__device__ float g_q  [BH*SEQ*HS];          // fp32 q (feeds sim)
__device__ float g_k  [BH*SEQ*HS];          // fp32 k (feeds sim + DPP gram)
__device__ float g_v  [BH*SEQ*HS];          // fp32 v
__device__ float g_sim[(size_t)BH*SEQ*SEQ]; // q_i . k_j
__device__ float g_y  [BATCH*SEQ*CDIM];     // attention output

// tf32 split operands (stored as fp32 bit patterns)
__device__ float g_xh [BATCH*SEQ*CDIM],  g_xl [BATCH*SEQ*CDIM];
__device__ float g_Wah[CDIM*3*CDIM],     g_Wal[CDIM*3*CDIM];
__device__ float g_Wph[CDIM*CDIM],       g_Wpl[CDIM*CDIM];
__device__ float g_yh [BATCH*SEQ*CDIM],  g_yl [BATCH*SEQ*CDIM];

// ---------------- helpers ----------------
__device__ __forceinline__ float tf32_rnd(float x)
{
    unsigned r;
    asm("cvt.rna.tf32.f32 %0, %1;" : "=r"(r) : "f"(x));
    return __uint_as_float(r);
}

__device__ __forceinline__ void mma_tf32(float* c, const float* a, float b0, float b1)
{
    asm volatile("mma.sync.aligned.m16n8k8.row.col.f32.tf32.tf32.f32 "
        "{%0,%1,%2,%3}, {%4,%5,%6,%7}, {%8,%9}, {%0,%1,%2,%3};"
        : "+f"(c[0]), "+f"(c[1]), "+f"(c[2]), "+f"(c[3])
        : "r"(__float_as_uint(a[0])), "r"(__float_as_uint(a[1])),
          "r"(__float_as_uint(a[2])), "r"(__float_as_uint(a[3])),
          "r"(__float_as_uint(b0)),   "r"(__float_as_uint(b1)));
}

// ---------------- split kernel: fp32 -> (hi,lo) tf32 pair ----------------
__global__ __launch_bounds__(256)
void split_kernel(const float* __restrict__ src, int which, int n)
{
    int i = (blockIdx.x*256 + threadIdx.x) * 4;
    if (i >= n) return;
    const float* s = src ? src : g_y;
    float *hi, *lo;
    switch (which) {
        case 0: hi = g_xh;  lo = g_xl;  break;
        case 1: hi = g_Wah; lo = g_Wal; break;
        case 2: hi = g_Wph; lo = g_Wpl; break;
        default: hi = g_yh; lo = g_yl;  break;
    }
    float4 v = *(const float4*)(s + i);
    float4 h, l;
    h.x = tf32_rnd(v.x); l.x = tf32_rnd(v.x - h.x);
    h.y = tf32_rnd(v.y); l.y = tf32_rnd(v.y - h.y);
    h.z = tf32_rnd(v.z); l.z = tf32_rnd(v.z - h.z);
    h.w = tf32_rnd(v.w); l.w = tf32_rnd(v.w - h.w);
    *(float4*)&hi[i] = h;
    *(float4*)&lo[i] = l;
}

// ---------------- qkv scatter ----------------
__device__ __forceinline__ void scatter_qkv(int row, int gc, float v0, float v1)
{
    int sect = gc / CDIM;              // 0=q 1=k 2=v
    int cc = gc - sect*CDIM;
    int h = cc >> 6, dd = cc & 63;
    int bb = row >> 9, t = row & 511;
    size_t off = ((size_t)(bb*NHEAD + h)*SEQ + t)*HS + dd;
    float* dst = (sect == 0) ? g_q : (sect == 1 ? g_k : g_v);
    *(float2*)&dst[off] = make_float2(v0, v1);
}

// ---------------- 3xTF32 GEMM: C[M,N] = A@B + bias ----------------
// mode 0: qkv (scatter)   mode 1: plain store to Cout
#define APITCH 20
#define BPITCH 136

__global__ __launch_bounds__(256)
void tf32_gemm(const float* __restrict__ bias, float* __restrict__ Cout,
               int M, int N, int K, int mode)
{
    __shared__ __align__(16) float As[2][128*APITCH];  // [split][m*20+k]
    __shared__ __align__(16) float Bs[2][16*BPITCH];   // [split][k*136+n]

    const float *Ah, *Al, *Bh, *Bl;
    if (mode == 0) { Ah = g_xh; Al = g_xl; Bh = g_Wah; Bl = g_Wal; }
    else           { Ah = g_yh; Al = g_yl; Bh = g_Wph; Bl = g_Wpl; }

    const int tid = threadIdx.x, lane = tid & 31, wid = tid >> 5;
    const int bm = blockIdx.y, bn = blockIdx.x;
    const int wm = wid & 3, wn = wid >> 2;
    const int g = lane >> 2, t = lane & 3;

    // loader coords: A ids tid*2, tid*2+1 ; B same
    const int ida0 = tid*2, ida1 = tid*2 + 1;
    const int ra0 = ida0 >> 2, ca0 = (ida0 & 3)*4;
    const int ra1 = ida1 >> 2, ca1 = (ida1 & 3)*4;
    const int kb0 = ida0 >> 5, nb0 = (ida0 & 31)*4;
    const int kb1 = ida1 >> 5, nb1 = (ida1 & 31)*4;

    float acc[2][8][4];
#pragma unroll
    for (int a = 0; a < 2; a++)
#pragma unroll
        for (int b = 0; b < 8; b++)
#pragma unroll
            for (int c = 0; c < 4; c++) acc[a][b][c] = 0.f;

    uint4 rah0, rah1, ral0, ral1, rbh0, rbh1, rbl0, rbl1;
    // prologue: chunk 0
    rah0 = *(const uint4*)&Ah[(size_t)(bm*128 + ra0)*K + ca0];
    rah1 = *(const uint4*)&Ah[(size_t)(bm*128 + ra1)*K + ca1];
    ral0 = *(const uint4*)&Al[(size_t)(bm*128 + ra0)*K + ca0];
    ral1 = *(const uint4*)&Al[(size_t)(bm*128 + ra1)*K + ca1];
    rbh0 = *(const uint4*)&Bh[(size_t)kb0*N + bn*128 + nb0];
    rbh1 = *(const uint4*)&Bh[(size_t)kb1*N + bn*128 + nb1];
    rbl0 = *(const uint4*)&Bl[(size_t)kb0*N + bn*128 + nb0];
    rbl1 = *(const uint4*)&Bl[(size_t)kb1*N + bn*128 + nb1];

    for (int k0 = 0; k0 < K; k0 += 16) {
        __syncthreads();
        *(uint4*)&As[0][ra0*APITCH + ca0] = rah0;
        *(uint4*)&As[0][ra1*APITCH + ca1] = rah1;
        *(uint4*)&As[1][ra0*APITCH + ca0] = ral0;
        *(uint4*)&As[1][ra1*APITCH + ca1] = ral1;
        *(uint4*)&Bs[0][kb0*BPITCH + nb0] = rbh0;
        *(uint4*)&Bs[0][kb1*BPITCH + nb1] = rbh1;
        *(uint4*)&Bs[1][kb0*BPITCH + nb0] = rbl0;
        *(uint4*)&Bs[1][kb1*BPITCH + nb1] = rbl1;
        __syncthreads();

        if (k0 + 16 < K) {
            int kn = k0 + 16;
            rah0 = *(const uint4*)&Ah[(size_t)(bm*128 + ra0)*K + kn + ca0];
            rah1 = *(const uint4*)&Ah[(size_t)(bm*128 + ra1)*K + kn + ca1];
            ral0 = *(const uint4*)&Al[(size_t)(bm*128 + ra0)*K + kn + ca0];
            ral1 = *(const uint4*)&Al[(size_t)(bm*128 + ra1)*K + kn + ca1];
            rbh0 = *(const uint4*)&Bh[(size_t)(kn + kb0)*N + bn*128 + nb0];
            rbh1 = *(const uint4*)&Bh[(size_t)(kn + kb1)*N + bn*128 + nb1];
            rbl0 = *(const uint4*)&Bl[(size_t)(kn + kb0)*N + bn*128 + nb0];
            rbl1 = *(const uint4*)&Bl[(size_t)(kn + kb1)*N + bn*128 + nb1];
        }

#pragma unroll
        for (int ks = 0; ks < 16; ks += 8) {
            float ah[2][4], al[2][4];
#pragma unroll
            for (int mt = 0; mt < 2; mt++) {
                int m0 = (wm*32 + mt*16 + g)*APITCH + ks + t;
                int m1 = m0 + 8*APITCH;
                ah[mt][0] = As[0][m0];   ah[mt][1] = As[0][m1];
                ah[mt][2] = As[0][m0+4]; ah[mt][3] = As[0][m1+4];
                al[mt][0] = As[1][m0];   al[mt][1] = As[1][m1];
                al[mt][2] = As[1][m0+4]; al[mt][3] = As[1][m1+4];
            }
#pragma unroll
            for (int nt = 0; nt < 8; nt++) {
                int nb = wn*64 + nt*8 + g;
                float bh0 = Bs[0][(ks+t)*BPITCH + nb];
                float bh1 = Bs[0][(ks+t+4)*BPITCH + nb];
                float bl0 = Bs[1][(ks+t)*BPITCH + nb];
                float bl1 = Bs[1][(ks+t+4)*BPITCH + nb];
#pragma unroll
                for (int mt = 0; mt < 2; mt++) {
                    mma_tf32(acc[mt][nt], ah[mt], bh0, bh1);
                    mma_tf32(acc[mt][nt], ah[mt], bl0, bl1);
                    mma_tf32(acc[mt][nt], al[mt], bh0, bh1);
                }
            }
        }
    }

    // epilogue: c0,c1 = (g,2t),(g,2t+1); c2,c3 = (g+8, ...)
#pragma unroll
    for (int mt = 0; mt < 2; mt++) {
        int r0 = bm*128 + wm*32 + mt*16 + g;
#pragma unroll
        for (int nt = 0; nt < 8; nt++) {
            int gc = bn*128 + wn*64 + nt*8 + t*2;
            float b0 = bias[gc], b1 = bias[gc+1];
            float v00 = acc[mt][nt][0] + b0, v01 = acc[mt][nt][1] + b1;
            float v10 = acc[mt][nt][2] + b0, v11 = acc[mt][nt][3] + b1;
            if (mode == 1) {
                *(float2*)&Cout[(size_t)r0*N + gc]     = make_float2(v00, v01);
                *(float2*)&Cout[(size_t)(r0+8)*N + gc] = make_float2(v10, v11);
            } else {
                scatter_qkv(r0,     gc, v00, v01);
                scatter_qkv(r0 + 8, gc, v10, v11);
            }
        }
    }
}

// ---------------- sim: S = Q K^T per head, 3xTF32 ----------------
__global__ __launch_bounds__(256)
void sim_tf32()
{
    const int bm = blockIdx.y, bn = blockIdx.x;
    if (bn > bm) return;                        // causal blocks only
    const int bh = blockIdx.z;

    __shared__ __align__(16) float Qs[2][128*APITCH];  // [split][m*20+k]
    __shared__ __align__(16) float Ks[2][128*APITCH];  // [split][n*20+k]

    const float* __restrict__ qb = g_q + (size_t)bh*SEQ*HS;
    const float* __restrict__ kb = g_k + (size_t)bh*SEQ*HS;

    const int tid = threadIdx.x, lane = tid & 31, wid = tid >> 5;
    const int wm = wid & 3, wn = wid >> 2;
    const int g = lane >> 2, t = lane & 3;

    float acc[2][8][4];
#pragma unroll
    for (int a = 0; a < 2; a++)
#pragma unroll
        for (int b = 0; b < 8; b++)
#pragma unroll
            for (int c = 0; c < 4; c++) acc[a][b][c] = 0.f;

    for (int d0 = 0; d0 < HS; d0 += 16) {
        if (d0 > 0) __syncthreads();
        // producer: convert fp32 -> tf32 hi/lo on the fly
#pragma unroll
        for (int j = 0; j < 2; j++) {
            int id = tid*2 + j;
            int r = id >> 2, c = (id & 3)*4;
            float4 qv = *(const float4*)&qb[(size_t)(bm*128 + r)*HS + d0 + c];
            float4 kv = *(const float4*)&kb[(size_t)(bn*128 + r)*HS + d0 + c];
            float4 qh, ql, kh, kl;
            qh.x = tf32_rnd(qv.x); ql.x = tf32_rnd(qv.x - qh.x);
            qh.y = tf32_rnd(qv.y); ql.y = tf32_rnd(qv.y - qh.y);
            qh.z = tf32_rnd(qv.z); ql.z = tf32_rnd(qv.z - qh.z);
            qh.w = tf32_rnd(qv.w); ql.w = tf32_rnd(qv.w - qh.w);
            kh.x = tf32_rnd(kv.x); kl.x = tf32_rnd(kv.x - kh.x);
            kh.y = tf32_rnd(kv.y); kl.y = tf32_rnd(kv.y - kh.y);
            kh.z = tf32_rnd(kv.z); kl.z = tf32_rnd(kv.z - kh.z);
            kh.w = tf32_rnd(kv.w); kl.w = tf32_rnd(kv.w - kh.w);
            *(float4*)&Qs[0][r*APITCH + c] = qh;
            *(float4*)&Qs[1][r*APITCH + c] = ql;
            *(float4*)&Ks[0][r*APITCH + c] = kh;
            *(float4*)&Ks[1][r*APITCH + c] = kl;
        }
        __syncthreads();

#pragma unroll
        for (int ks = 0; ks < 16; ks += 8) {
            float ah[2][4], al[2][4];
#pragma unroll
            for (int mt = 0; mt < 2; mt++) {
                int m0 = (wm*32 + mt*16 + g)*APITCH + ks + t;
                int m1 = m0 + 8*APITCH;
                ah[mt][0] = Qs[0][m0];   ah[mt][1] = Qs[0][m1];
                ah[mt][2] = Qs[0][m0+4]; ah[mt][3] = Qs[0][m1+4];
                al[mt][0] = Qs[1][m0];   al[mt][1] = Qs[1][m1];
                al[mt][2] = Qs[1][m0+4]; al[mt][3] = Qs[1][m1+4];
            }
#pragma unroll
            for (int nt = 0; nt < 8; nt++) {
                int n0 = (wn*64 + nt*8 + g)*APITCH + ks + t;
                float bh0 = Ks[0][n0];
                float bh1 = Ks[0][n0+4];
                float bl0 = Ks[1][n0];
                float bl1 = Ks[1][n0+4];
#pragma unroll
                for (int mt = 0; mt < 2; mt++) {
                    mma_tf32(acc[mt][nt], ah[mt], bh0, bh1);
                    mma_tf32(acc[mt][nt], ah[mt], bl0, bl1);
                    mma_tf32(acc[mt][nt], al[mt], bh0, bh1);
                }
            }
        }
    }

    float* S = g_sim + (size_t)bh*SEQ*SEQ;
#pragma unroll
    for (int mt = 0; mt < 2; mt++) {
        int r0 = bm*128 + wm*32 + mt*16 + g;
#pragma unroll
        for (int nt = 0; nt < 8; nt++) {
            int gc = bn*128 + wn*64 + nt*8 + t*2;
            *(float2*)&S[(size_t)r0*SEQ + gc]     = make_float2(acc[mt][nt][0], acc[mt][nt][1]);
            *(float2*)&S[(size_t)(r0+8)*SEQ + gc] = make_float2(acc[mt][nt][2], acc[mt][nt][3]);
        }
    }
}

// ---------------- DPP greedy selection (unchanged, proven) ----------------
__global__ __launch_bounds__(32*DW)
void dpp_kernel()
{
    __shared__ __align__(16) float krows[DW][17][68];
    __shared__ float Gm[DW][17][17];

    const unsigned FULL = 0xffffffffu;
    const int lane = threadIdx.x & 31;
    const int wrp  = threadIdx.x >> 5;
    const int i  = blockIdx.x * DW + wrp;
    const int bh = blockIdx.y;
    const int nvalid = i + 1;

    const float* __restrict__ kb = g_k + (size_t)bh*SEQ*HS;
    const float* __restrict__ vb = g_v + (size_t)bh*SEQ*HS;
    const float* __restrict__ simRow = g_sim + ((size_t)bh*SEQ + i)*SEQ;

    float val[16];
#pragma unroll
    for (int c = 0; c < 16; c++) {
        int idx = c*32 + lane;
        val[c] = (idx < nvalid) ? simRow[idx] : -INFINITY;
    }

    float myVal = -INFINITY; int myIdx = i;
    for (int t = 0; t < 16; t++) {
        float bv = val[0]; int bc = 0;
#pragma unroll
        for (int c = 1; c < 16; c++) if (val[c] > bv) { bv = val[c]; bc = c; }
        int bg = bc*32 + lane;
#pragma unroll
        for (int off = 16; off; off >>= 1) {
            float ov = __shfl_down_sync(FULL, bv, off);
            int   og = __shfl_down_sync(FULL, bg, off);
            if (ov > bv || (ov == bv && og < bg)) { bv = ov; bg = og; }
        }
        bv = __shfl_sync(FULL, bv, 0);
        bg = __shfl_sync(FULL, bg, 0);
        if (lane == (bg & 31)) {
            int cc = bg >> 5;
#pragma unroll
            for (int c = 0; c < 16; c++) if (c == cc) val[c] = -INFINITY;
        }
        if (lane == t) { myVal = bv; myIdx = bg; }
    }
    bool availb = (lane < 16) && (myVal > -INFINITY) && (myIdx != i);
    unsigned avail = __ballot_sync(FULL, availb) & 0xFFFFu;
    int safeIdx = (lane < 16 && myVal > -INFINITY) ? myIdx : i;

    const int half = lane >> 4;
    const int hl   = lane & 15;
    for (int r = 0; r < 17; r += 2) {
        int src = r + half;
        int sl  = src & 15;
        int gv  = __shfl_sync(FULL, safeIdx, sl);
        int gidx = (src >= 16) ? i : gv;
        if (src <= 16) {
            float4 kv = ((const float4*)(kb + (size_t)gidx*HS))[hl];
            *(float4*)&krows[wrp][src][hl*4] = kv;
        }
    }
    __syncwarp();

#pragma unroll
    for (int t = 0; t < 10; t++) {
        int e = lane + 32*t;
        if (e < 289) {
            int a = e / 17, b = e - a*17;
            if (a <= b) {
                const float* ra = krows[wrp][a];
                const float* rb = krows[wrp][b];
                float acc = 0.f;
#pragma unroll
                for (int c = 0; c < 16; c++) {
                    float4 x = ((const float4*)ra)[c];
                    float4 y = ((const float4*)rb)[c];
                    acc = fmaf(x.x, y.x, acc);
                    acc = fmaf(x.y, y.y, acc);
                    acc = fmaf(x.z, y.z, acc);
                    acc = fmaf(x.w, y.w, acc);
                }
                Gm[wrp][a][b] = acc;
                Gm[wrp][b][a] = acc;
            }
        }
    }
    __syncwarp();

    const int cl = lane & 15;
    float Gii  = Gm[wrp][16][16];
    float detS = Gii;
    float curS = -logf(Gii + 1e-6f);
    int count = 1;
    float w[8];
    float w0 = Gm[wrp][cl][16] / sqrtf(Gii);
    w[0] = w0;
#pragma unroll
    for (int j = 1; j < 8; j++) w[j] = 0.f;
    float ec = Gm[wrp][cl][cl] - w0*w0;
    int selTok[8];
#pragma unroll
    for (int j = 0; j < 8; j++) selTok[j] = i;

    for (int step = 0; step < 7; step++) {
        bool av = (lane < 16) && ((avail >> lane) & 1u);
        float s = av ? (-logf(detS*ec + 1e-6f) / (float)(count + 1)) : -INFINITY;
        float bs = s; int bl = lane;
#pragma unroll
        for (int off = 16; off; off >>= 1) {
            float ov = __shfl_down_sync(FULL, bs, off);
            int   ol = __shfl_down_sync(FULL, bl, off);
            bool nb = isnan(bs), no = isnan(ov);
            bool better = (!nb && (no || ov > bs)) ||
                          (((nb && no) || (ov == bs)) && ol < bl);
            if (better) { bs = ov; bl = ol; }
        }
        bs = __shfl_sync(FULL, bs, 0);
        bl = __shfl_sync(FULL, bl, 0);
        bool anyAvail = (avail != 0u);
        bool accept = anyAvail && ((bs > curS) || (count < 2));
        if (!accept) break;

        float eb = __shfl_sync(FULL, ec, bl);
        float Lb = sqrtf(eb);
        float dot = 0.f;
#pragma unroll
        for (int j = 0; j < 7; j++) {
            float wbj = __shfl_sync(FULL, w[j], bl);
            if (j < count) dot += w[j]*wbj;
        }
        float wn = (Gm[wrp][cl][bl] - dot) / Lb;
#pragma unroll
        for (int j = 1; j < 8; j++) if (j == count) w[j] = wn;
        ec -= wn*wn;
        detS *= eb;
        curS = bs;
        int btok = __shfl_sync(FULL, myIdx, bl);
#pragma unroll
        for (int j = 1; j < 8; j++) if (j == count) selTok[j] = btok;
        count++;
        avail &= ~(1u << bl);
    }

    float a0 = 0.f, a1 = 0.f;
#pragma unroll
    for (int r = 0; r < 8; r++) {
        if (r < count) {
            const float* vr = vb + (size_t)selTok[r]*HS;
            a0 += vr[lane];
            a1 += vr[lane + 32];
        }
    }
    float cnt = (float)count;
    int bb = bh / NHEAD, h = bh % NHEAD;
    float* yo = g_y + ((size_t)(bb*SEQ + i))*CDIM + h*HS;
    yo[lane]      = a0 / cnt;
    yo[lane + 32] = a1 / cnt;
}

// ---------------------------------------------------------------------------
extern "C" void kernel_launch(void* const* d_in, const int* in_sizes, int n_in,
                              void* d_out, int out_size)
{
    const float* x      = (const float*)d_in[0];
    const float* W_attn = (const float*)d_in[1];
    const float* b_attn = (const float*)d_in[2];
    const float* W_proj = (const float*)d_in[3];
    const float* b_proj = (const float*)d_in[4];
    float* out = (float*)d_out;

    const int nx  = BATCH*SEQ*CDIM;      // 1572864
    const int nwa = CDIM*3*CDIM;         // 1769472
    const int nwp = CDIM*CDIM;           // 589824

    split_kernel<<<(nx/4 + 255)/256, 256>>>(x, 0, nx);
    split_kernel<<<(nwa/4 + 255)/256, 256>>>(W_attn, 1, nwa);
    split_kernel<<<(nwp/4 + 255)/256, 256>>>(W_proj, 2, nwp);

    {   // QKV: [2048,768] @ [768,2304] -> scatter q/k/v (fp32)
        dim3 grid(3*CDIM/128, (BATCH*SEQ)/128);
        tf32_gemm<<<grid, 256>>>(b_attn, out, BATCH*SEQ, 3*CDIM, CDIM, 0);
    }
    {   // sim: S = Q K^T per head (lower-tri blocks)
        dim3 grid(4, 4, BH);
        sim_tf32<<<grid, 256>>>();
    }
    {   // DPP attention -> g_y
        dim3 grid(SEQ/DW, BH);
        dpp_kernel<<<grid, 32*DW>>>();
    }
    split_kernel<<<(nx/4 + 255)/256, 256>>>(nullptr, 3, nx);   // y -> yh/yl
    {   // Proj: [2048,768] @ [768,768] -> out
        dim3 grid(CDIM/128, (BATCH*SEQ)/128);
        tf32_gemm<<<grid, 256>>>(b_proj, out, BATCH*SEQ, CDIM, CDIM, 1);
    }
}

// round 7
// speedup vs baseline: 6.0447x; 1.0324x over previous
#include <cuda_runtime.h>
#include <cuda_bf16.h>
#include <math.h>
#include <float.h>

#define BATCH 4
#define SEQ   512
#define CDIM  768
#define NHEAD 12
#define HS    64
#define BH    (BATCH*NHEAD)      // 48
#define DW    8                  // warps (tokens) per dpp block

// ---------------- device scratch (allocation forbidden) ----------------
__device__ float g_q  [BH*SEQ*HS];          // fp32 q (feeds sim)
__device__ float g_k  [BH*SEQ*HS];          // fp32 k (feeds sim + DPP gram)
__device__ float g_v  [BH*SEQ*HS];          // fp32 v
__device__ float g_sim[(size_t)BH*SEQ*SEQ]; // q_i . k_j
__device__ float g_y  [BATCH*SEQ*CDIM];     // attention output

// tf32 split operands (stored as fp32 bit patterns)
__device__ float g_xh [BATCH*SEQ*CDIM],  g_xl [BATCH*SEQ*CDIM];
__device__ float g_Wah[CDIM*3*CDIM],     g_Wal[CDIM*3*CDIM];
__device__ float g_Wph[CDIM*CDIM],       g_Wpl[CDIM*CDIM];
__device__ float g_yh [BATCH*SEQ*CDIM],  g_yl [BATCH*SEQ*CDIM];

// ---------------- helpers ----------------
__device__ __forceinline__ float tf32_rnd(float x)
{
    unsigned r;
    asm("cvt.rna.tf32.f32 %0, %1;" : "=r"(r) : "f"(x));
    return __uint_as_float(r);
}

__device__ __forceinline__ void mma_tf32(float* c, const float* a, float b0, float b1)
{
    asm volatile("mma.sync.aligned.m16n8k8.row.col.f32.tf32.tf32.f32 "
        "{%0,%1,%2,%3}, {%4,%5,%6,%7}, {%8,%9}, {%0,%1,%2,%3};"
        : "+f"(c[0]), "+f"(c[1]), "+f"(c[2]), "+f"(c[3])
        : "r"(__float_as_uint(a[0])), "r"(__float_as_uint(a[1])),
          "r"(__float_as_uint(a[2])), "r"(__float_as_uint(a[3])),
          "r"(__float_as_uint(b0)),   "r"(__float_as_uint(b1)));
}

__device__ __forceinline__ void cp16(unsigned dst, const float* src)
{
    asm volatile("cp.async.ca.shared.global [%0], [%1], 16;" :: "r"(dst), "l"(src));
}

// ---------------- split kernel: fp32 -> (hi,lo) tf32 pair ----------------
__global__ __launch_bounds__(256)
void split_kernel(const float* __restrict__ src, int which, int n)
{
    int i = (blockIdx.x*256 + threadIdx.x) * 4;
    if (i >= n) return;
    const float* s = src ? src : g_y;
    float *hi, *lo;
    switch (which) {
        case 0: hi = g_xh;  lo = g_xl;  break;
        case 1: hi = g_Wah; lo = g_Wal; break;
        case 2: hi = g_Wph; lo = g_Wpl; break;
        default: hi = g_yh; lo = g_yl;  break;
    }
    float4 v = *(const float4*)(s + i);
    float4 h, l;
    h.x = tf32_rnd(v.x); l.x = tf32_rnd(v.x - h.x);
    h.y = tf32_rnd(v.y); l.y = tf32_rnd(v.y - h.y);
    h.z = tf32_rnd(v.z); l.z = tf32_rnd(v.z - h.z);
    h.w = tf32_rnd(v.w); l.w = tf32_rnd(v.w - h.w);
    *(float4*)&hi[i] = h;
    *(float4*)&lo[i] = l;
}

// ---------------- qkv scatter ----------------
__device__ __forceinline__ void scatter_qkv(int row, int gc, float v0, float v1)
{
    int sect = gc / CDIM;              // 0=q 1=k 2=v
    int cc = gc - sect*CDIM;
    int h = cc >> 6, dd = cc & 63;
    int bb = row >> 9, t = row & 511;
    size_t off = ((size_t)(bb*NHEAD + h)*SEQ + t)*HS + dd;
    float* dst = (sect == 0) ? g_q : (sect == 1 ? g_k : g_v);
    *(float2*)&dst[off] = make_float2(v0, v1);
}

// ---------------- 3xTF32 GEMM, cp.async 2-stage pipeline ----------------
// CTA 128x128, K-chunk 8. Stage layout (floats):
//   A: [split][m(128)][pitch 12, k 0..7]        at 0      (3072 floats)
//   B: [split][k(8)][pitch 136, n 0..127]       at 3072   (2176 floats)
#define STG 5248

__global__ __launch_bounds__(256, 2)
void tf32_gemm(const float* __restrict__ bias, float* __restrict__ Cout,
               int M, int N, int K, int mode)
{
    __shared__ __align__(16) float sm[2*STG];

    const float *Ah, *Al, *Bh, *Bl;
    if (mode == 0) { Ah = g_xh; Al = g_xl; Bh = g_Wah; Bl = g_Wal; }
    else           { Ah = g_yh; Al = g_yl; Bh = g_Wph; Bl = g_Wpl; }

    const int tid = threadIdx.x, lane = tid & 31, wid = tid >> 5;
    const int bm = blockIdx.y, bn = blockIdx.x;
    const int wm = wid & 3, wn = wid >> 2;
    const int g = lane >> 2, t = lane & 3;

    const unsigned smbase = (unsigned)__cvta_generic_to_shared(sm);

    // per-thread copy coords (ids tid and tid+256)
    int aSp[2], aM[2], aKq[2], bSp[2], bK[2], bN4[2];
#pragma unroll
    for (int h = 0; h < 2; h++) {
        int id = tid + h*256;
        aSp[h] = id >> 8; int ra = id & 255; aM[h] = ra >> 1; aKq[h] = (ra & 1) * 4;
        bSp[h] = id >> 8; int rb = id & 255; bK[h] = rb >> 5; bN4[h] = (rb & 31) * 4;
    }

    float acc[2][8][4];
#pragma unroll
    for (int a = 0; a < 2; a++)
#pragma unroll
        for (int b = 0; b < 8; b++)
#pragma unroll
            for (int c = 0; c < 4; c++) acc[a][b][c] = 0.f;

    const int NC = K >> 3;

    // ---- stage issue ----
    auto issue = [&](int s, int k0) {
        unsigned base = smbase + (unsigned)(s*STG)*4u;
#pragma unroll
        for (int h = 0; h < 2; h++) {
            const float* srcA = (aSp[h] ? Al : Ah) + (size_t)(bm*128 + aM[h])*K + k0 + aKq[h];
            cp16(base + (unsigned)(aSp[h]*1536 + aM[h]*12 + aKq[h])*4u, srcA);
        }
#pragma unroll
        for (int h = 0; h < 2; h++) {
            const float* srcB = (bSp[h] ? Bl : Bh) + (size_t)(k0 + bK[h])*N + bn*128 + bN4[h];
            cp16(base + (unsigned)(3072 + bSp[h]*1088 + bK[h]*136 + bN4[h])*4u, srcB);
        }
        asm volatile("cp.async.commit_group;");
    };

    issue(0, 0);

    for (int c = 0; c < NC; c++) {
        if (c + 1 < NC) {
            issue((c+1) & 1, (c+1)*8);
            asm volatile("cp.async.wait_group 1;");
        } else {
            asm volatile("cp.async.wait_group 0;");
        }
        __syncthreads();

        const float* S = sm + (c & 1)*STG;

        float ah[2][4], al[2][4];
#pragma unroll
        for (int mt = 0; mt < 2; mt++) {
            int m0 = (wm*32 + mt*16 + g)*12 + t;
            ah[mt][0] = S[m0];          ah[mt][1] = S[m0 + 96];      // +8 rows
            ah[mt][2] = S[m0 + 4];      ah[mt][3] = S[m0 + 100];
            al[mt][0] = S[1536 + m0];   al[mt][1] = S[1536 + m0 + 96];
            al[mt][2] = S[1536 + m0+4]; al[mt][3] = S[1536 + m0 + 100];
        }
#pragma unroll
        for (int nt = 0; nt < 8; nt++) {
            int nb = wn*64 + nt*8 + g;
            float bh0 = S[3072 + t*136 + nb];
            float bh1 = S[3072 + (t+4)*136 + nb];
            float bl0 = S[4160 + t*136 + nb];
            float bl1 = S[4160 + (t+4)*136 + nb];
#pragma unroll
            for (int mt = 0; mt < 2; mt++) {
                mma_tf32(acc[mt][nt], ah[mt], bh0, bh1);
                mma_tf32(acc[mt][nt], ah[mt], bl0, bl1);
                mma_tf32(acc[mt][nt], al[mt], bh0, bh1);
            }
        }
        __syncthreads();
    }

    // epilogue
#pragma unroll
    for (int mt = 0; mt < 2; mt++) {
        int r0 = bm*128 + wm*32 + mt*16 + g;
#pragma unroll
        for (int nt = 0; nt < 8; nt++) {
            int gc = bn*128 + wn*64 + nt*8 + t*2;
            float b0 = bias[gc], b1 = bias[gc+1];
            float v00 = acc[mt][nt][0] + b0, v01 = acc[mt][nt][1] + b1;
            float v10 = acc[mt][nt][2] + b0, v11 = acc[mt][nt][3] + b1;
            if (mode == 1) {
                *(float2*)&Cout[(size_t)r0*N + gc]     = make_float2(v00, v01);
                *(float2*)&Cout[(size_t)(r0+8)*N + gc] = make_float2(v10, v11);
            } else {
                scatter_qkv(r0,     gc, v00, v01);
                scatter_qkv(r0 + 8, gc, v10, v11);
            }
        }
    }
}

// ---------------- sim: S = Q K^T per head, 3xTF32 ----------------
#define APITCH 20
__global__ __launch_bounds__(256)
void sim_tf32()
{
    const int bm = blockIdx.y, bn = blockIdx.x;
    if (bn > bm) return;                        // causal blocks only
    const int bh = blockIdx.z;

    __shared__ __align__(16) float Qs[2][128*APITCH];
    __shared__ __align__(16) float Ks[2][128*APITCH];

    const float* __restrict__ qb = g_q + (size_t)bh*SEQ*HS;
    const float* __restrict__ kb = g_k + (size_t)bh*SEQ*HS;

    const int tid = threadIdx.x, lane = tid & 31, wid = tid >> 5;
    const int wm = wid & 3, wn = wid >> 2;
    const int g = lane >> 2, t = lane & 3;

    float acc[2][8][4];
#pragma unroll
    for (int a = 0; a < 2; a++)
#pragma unroll
        for (int b = 0; b < 8; b++)
#pragma unroll
            for (int c = 0; c < 4; c++) acc[a][b][c] = 0.f;

    for (int d0 = 0; d0 < HS; d0 += 16) {
        if (d0 > 0) __syncthreads();
#pragma unroll
        for (int j = 0; j < 2; j++) {
            int id = tid*2 + j;
            int r = id >> 2, c = (id & 3)*4;
            float4 qv = *(const float4*)&qb[(size_t)(bm*128 + r)*HS + d0 + c];
            float4 kv = *(const float4*)&kb[(size_t)(bn*128 + r)*HS + d0 + c];
            float4 qh, ql, kh, kl;
            qh.x = tf32_rnd(qv.x); ql.x = tf32_rnd(qv.x - qh.x);
            qh.y = tf32_rnd(qv.y); ql.y = tf32_rnd(qv.y - qh.y);
            qh.z = tf32_rnd(qv.z); ql.z = tf32_rnd(qv.z - qh.z);
            qh.w = tf32_rnd(qv.w); ql.w = tf32_rnd(qv.w - qh.w);
            kh.x = tf32_rnd(kv.x); kl.x = tf32_rnd(kv.x - kh.x);
            kh.y = tf32_rnd(kv.y); kl.y = tf32_rnd(kv.y - kh.y);
            kh.z = tf32_rnd(kv.z); kl.z = tf32_rnd(kv.z - kh.z);
            kh.w = tf32_rnd(kv.w); kl.w = tf32_rnd(kv.w - kh.w);
            *(float4*)&Qs[0][r*APITCH + c] = qh;
            *(float4*)&Qs[1][r*APITCH + c] = ql;
            *(float4*)&Ks[0][r*APITCH + c] = kh;
            *(float4*)&Ks[1][r*APITCH + c] = kl;
        }
        __syncthreads();

#pragma unroll
        for (int ks = 0; ks < 16; ks += 8) {
            float ah[2][4], al[2][4];
#pragma unroll
            for (int mt = 0; mt < 2; mt++) {
                int m0 = (wm*32 + mt*16 + g)*APITCH + ks + t;
                int m1 = m0 + 8*APITCH;
                ah[mt][0] = Qs[0][m0];   ah[mt][1] = Qs[0][m1];
                ah[mt][2] = Qs[0][m0+4]; ah[mt][3] = Qs[0][m1+4];
                al[mt][0] = Qs[1][m0];   al[mt][1] = Qs[1][m1];
                al[mt][2] = Qs[1][m0+4]; al[mt][3] = Qs[1][m1+4];
            }
#pragma unroll
            for (int nt = 0; nt < 8; nt++) {
                int n0 = (wn*64 + nt*8 + g)*APITCH + ks + t;
                float bh0 = Ks[0][n0];
                float bh1 = Ks[0][n0+4];
                float bl0 = Ks[1][n0];
                float bl1 = Ks[1][n0+4];
#pragma unroll
                for (int mt = 0; mt < 2; mt++) {
                    mma_tf32(acc[mt][nt], ah[mt], bh0, bh1);
                    mma_tf32(acc[mt][nt], ah[mt], bl0, bl1);
                    mma_tf32(acc[mt][nt], al[mt], bh0, bh1);
                }
            }
        }
    }

    float* S = g_sim + (size_t)bh*SEQ*SEQ;
#pragma unroll
    for (int mt = 0; mt < 2; mt++) {
        int r0 = bm*128 + wm*32 + mt*16 + g;
#pragma unroll
        for (int nt = 0; nt < 8; nt++) {
            int gc = bn*128 + wn*64 + nt*8 + t*2;
            *(float2*)&S[(size_t)r0*SEQ + gc]     = make_float2(acc[mt][nt][0], acc[mt][nt][1]);
            *(float2*)&S[(size_t)(r0+8)*SEQ + gc] = make_float2(acc[mt][nt][2], acc[mt][nt][3]);
        }
    }
}

// ---------------- DPP greedy selection (unchanged, proven) ----------------
__global__ __launch_bounds__(32*DW)
void dpp_kernel()
{
    __shared__ __align__(16) float krows[DW][17][68];
    __shared__ float Gm[DW][17][17];

    const unsigned FULL = 0xffffffffu;
    const int lane = threadIdx.x & 31;
    const int wrp  = threadIdx.x >> 5;
    const int i  = blockIdx.x * DW + wrp;
    const int bh = blockIdx.y;
    const int nvalid = i + 1;

    const float* __restrict__ kb = g_k + (size_t)bh*SEQ*HS;
    const float* __restrict__ vb = g_v + (size_t)bh*SEQ*HS;
    const float* __restrict__ simRow = g_sim + ((size_t)bh*SEQ + i)*SEQ;

    float val[16];
#pragma unroll
    for (int c = 0; c < 16; c++) {
        int idx = c*32 + lane;
        val[c] = (idx < nvalid) ? simRow[idx] : -INFINITY;
    }

    float myVal = -INFINITY; int myIdx = i;
    for (int t = 0; t < 16; t++) {
        float bv = val[0]; int bc = 0;
#pragma unroll
        for (int c = 1; c < 16; c++) if (val[c] > bv) { bv = val[c]; bc = c; }
        int bg = bc*32 + lane;
#pragma unroll
        for (int off = 16; off; off >>= 1) {
            float ov = __shfl_down_sync(FULL, bv, off);
            int   og = __shfl_down_sync(FULL, bg, off);
            if (ov > bv || (ov == bv && og < bg)) { bv = ov; bg = og; }
        }
        bv = __shfl_sync(FULL, bv, 0);
        bg = __shfl_sync(FULL, bg, 0);
        if (lane == (bg & 31)) {
            int cc = bg >> 5;
#pragma unroll
            for (int c = 0; c < 16; c++) if (c == cc) val[c] = -INFINITY;
        }
        if (lane == t) { myVal = bv; myIdx = bg; }
    }
    bool availb = (lane < 16) && (myVal > -INFINITY) && (myIdx != i);
    unsigned avail = __ballot_sync(FULL, availb) & 0xFFFFu;
    int safeIdx = (lane < 16 && myVal > -INFINITY) ? myIdx : i;

    const int half = lane >> 4;
    const int hl   = lane & 15;
    for (int r = 0; r < 17; r += 2) {
        int src = r + half;
        int sl  = src & 15;
        int gv  = __shfl_sync(FULL, safeIdx, sl);
        int gidx = (src >= 16) ? i : gv;
        if (src <= 16) {
            float4 kv = ((const float4*)(kb + (size_t)gidx*HS))[hl];
            *(float4*)&krows[wrp][src][hl*4] = kv;
        }
    }
    __syncwarp();

#pragma unroll
    for (int t = 0; t < 10; t++) {
        int e = lane + 32*t;
        if (e < 289) {
            int a = e / 17, b = e - a*17;
            if (a <= b) {
                const float* ra = krows[wrp][a];
                const float* rb = krows[wrp][b];
                float acc = 0.f;
#pragma unroll
                for (int c = 0; c < 16; c++) {
                    float4 x = ((const float4*)ra)[c];
                    float4 y = ((const float4*)rb)[c];
                    acc = fmaf(x.x, y.x, acc);
                    acc = fmaf(x.y, y.y, acc);
                    acc = fmaf(x.z, y.z, acc);
                    acc = fmaf(x.w, y.w, acc);
                }
                Gm[wrp][a][b] = acc;
                Gm[wrp][b][a] = acc;
            }
        }
    }
    __syncwarp();

    const int cl = lane & 15;
    float Gii  = Gm[wrp][16][16];
    float detS = Gii;
    float curS = -logf(Gii + 1e-6f);
    int count = 1;
    float w[8];
    float w0 = Gm[wrp][cl][16] / sqrtf(Gii);
    w[0] = w0;
#pragma unroll
    for (int j = 1; j < 8; j++) w[j] = 0.f;
    float ec = Gm[wrp][cl][cl] - w0*w0;
    int selTok[8];
#pragma unroll
    for (int j = 0; j < 8; j++) selTok[j] = i;

    for (int step = 0; step < 7; step++) {
        bool av = (lane < 16) && ((avail >> lane) & 1u);
        float s = av ? (-logf(detS*ec + 1e-6f) / (float)(count + 1)) : -INFINITY;
        float bs = s; int bl = lane;
#pragma unroll
        for (int off = 16; off; off >>= 1) {
            float ov = __shfl_down_sync(FULL, bs, off);
            int   ol = __shfl_down_sync(FULL, bl, off);
            bool nb = isnan(bs), no = isnan(ov);
            bool better = (!nb && (no || ov > bs)) ||
                          (((nb && no) || (ov == bs)) && ol < bl);
            if (better) { bs = ov; bl = ol; }
        }
        bs = __shfl_sync(FULL, bs, 0);
        bl = __shfl_sync(FULL, bl, 0);
        bool anyAvail = (avail != 0u);
        bool accept = anyAvail && ((bs > curS) || (count < 2));
        if (!accept) break;

        float eb = __shfl_sync(FULL, ec, bl);
        float Lb = sqrtf(eb);
        float dot = 0.f;
#pragma unroll
        for (int j = 0; j < 7; j++) {
            float wbj = __shfl_sync(FULL, w[j], bl);
            if (j < count) dot += w[j]*wbj;
        }
        float wn = (Gm[wrp][cl][bl] - dot) / Lb;
#pragma unroll
        for (int j = 1; j < 8; j++) if (j == count) w[j] = wn;
        ec -= wn*wn;
        detS *= eb;
        curS = bs;
        int btok = __shfl_sync(FULL, myIdx, bl);
#pragma unroll
        for (int j = 1; j < 8; j++) if (j == count) selTok[j] = btok;
        count++;
        avail &= ~(1u << bl);
    }

    float a0 = 0.f, a1 = 0.f;
#pragma unroll
    for (int r = 0; r < 8; r++) {
        if (r < count) {
            const float* vr = vb + (size_t)selTok[r]*HS;
            a0 += vr[lane];
            a1 += vr[lane + 32];
        }
    }
    float cnt = (float)count;
    int bb = bh / NHEAD, h = bh % NHEAD;
    float* yo = g_y + ((size_t)(bb*SEQ + i))*CDIM + h*HS;
    yo[lane]      = a0 / cnt;
    yo[lane + 32] = a1 / cnt;
}

// ---------------------------------------------------------------------------
extern "C" void kernel_launch(void* const* d_in, const int* in_sizes, int n_in,
                              void* d_out, int out_size)
{
    const float* x      = (const float*)d_in[0];
    const float* W_attn = (const float*)d_in[1];
    const float* b_attn = (const float*)d_in[2];
    const float* W_proj = (const float*)d_in[3];
    const float* b_proj = (const float*)d_in[4];
    float* out = (float*)d_out;

    const int nx  = BATCH*SEQ*CDIM;      // 1572864
    const int nwa = CDIM*3*CDIM;         // 1769472
    const int nwp = CDIM*CDIM;           // 589824

    split_kernel<<<(nx/4 + 255)/256, 256>>>(x, 0, nx);
    split_kernel<<<(nwa/4 + 255)/256, 256>>>(W_attn, 1, nwa);
    split_kernel<<<(nwp/4 + 255)/256, 256>>>(W_proj, 2, nwp);

    {   // QKV: [2048,768] @ [768,2304] -> scatter q/k/v (fp32)
        dim3 grid(3*CDIM/128, (BATCH*SEQ)/128);
        tf32_gemm<<<grid, 256>>>(b_attn, out, BATCH*SEQ, 3*CDIM, CDIM, 0);
    }
    {   // sim: S = Q K^T per head (lower-tri blocks)
        dim3 grid(4, 4, BH);
        sim_tf32<<<grid, 256>>>();
    }
    {   // DPP attention -> g_y
        dim3 grid(SEQ/DW, BH);
        dpp_kernel<<<grid, 32*DW>>>();
    }
    split_kernel<<<(nx/4 + 255)/256, 256>>>(nullptr, 3, nx);   // y -> yh/yl
    {   // Proj: [2048,768] @ [768,768] -> out
        dim3 grid(CDIM/128, (BATCH*SEQ)/128);
        tf32_gemm<<<grid, 256>>>(b_proj, out, BATCH*SEQ, CDIM, CDIM, 1);
    }
}